// round 14
// baseline (speedup 1.0000x reference)
#include <cuda_runtime.h>
#include <cuda_fp16.h>
#include <math.h>
#include <stdint.h>

#define FDIM 128
#define SSCALE 1.6666666666666667f   // 1/0.6
#define INV3 0.5773502691896258f     // 1/sqrt(3)
#define INVH 0.08838834764831845f    // 1/sqrt(128)

static __device__ float g_buf[127000000];

__device__ __forceinline__ float ssilu_f(float v) {
    return v * SSCALE / (1.0f + __expf(-v));
}

__device__ __forceinline__ uint32_t pack_h2(float a, float b) {
    __half2 h = __floats2half2_rn(a, b);
    return *reinterpret_cast<uint32_t*>(&h);
}

__device__ __forceinline__ uint32_t smem_to_u32(const void* smem_ptr) {
    uint32_t addr;
    asm("{ .reg .u64 tmp; cvta.to.shared.u64 tmp, %1; cvt.u32.u64 %0, tmp; }"
        : "=r"(addr) : "l"(smem_ptr));
    return addr;
}

__device__ __forceinline__ void ldsm_x4(uint32_t addr, uint32_t* r) {
    asm volatile("ldmatrix.sync.aligned.m8n8.x4.shared.b16 {%0,%1,%2,%3}, [%4];"
        : "=r"(r[0]), "=r"(r[1]), "=r"(r[2]), "=r"(r[3]) : "r"(addr));
}

__device__ __forceinline__ uint32_t lds_u32(uint32_t addr) {
    uint32_t v;
    asm volatile("ld.shared.b32 %0, [%1];" : "=r"(v) : "r"(addr));
    return v;
}

__device__ __forceinline__ void mma_f16(float* d, const uint32_t* a,
                                        const uint32_t* b, const float* c) {
    asm volatile(
        "mma.sync.aligned.m16n8k16.row.col.f32.f16.f16.f32 "
        "{%0,%1,%2,%3},{%4,%5,%6,%7},{%8,%9},{%10,%11,%12,%13};"
        : "=f"(d[0]), "=f"(d[1]), "=f"(d[2]), "=f"(d[3])
        : "r"(a[0]), "r"(a[1]), "r"(a[2]), "r"(a[3]),
          "r"(b[0]), "r"(b[1]),
          "f"(c[0]), "f"(c[1]), "f"(c[2]), "f"(c[3]));
}

__device__ __forceinline__ void cpa16(uint32_t dst, const void* src) {
    asm volatile("cp.async.cg.shared.global [%0], [%1], 16;" :: "r"(dst), "l"(src));
}
#define CP_COMMIT() asm volatile("cp.async.commit_group;" ::: "memory")
#define CP_WAIT0()  asm volatile("cp.async.wait_group 0;" ::: "memory")

__device__ __forceinline__ uint32_t sm_off(int row, int c) {
    uint32_t chunk = (uint32_t)(c & 31) >> 3;
    return (uint32_t)(c >> 5) * 8192 + row * 64
         + ((chunk ^ ((uint32_t)(row >> 1) & 3)) << 4) + ((c & 7) * 2);
}

template <int K>
__device__ __forceinline__ void load_tile(uint32_t sbase, const __half* G,
                                          int grow0, int M, int tid)
{
    constexpr int NCH = K / 8;
    #pragma unroll
    for (int t = 0; t < (128 * NCH) / 256; t++) {
        int id = tid + t * 256;
        int row = id / NCH;
        int ch = id % NCH;
        int ga = grow0 + row;
        if (ga >= M) ga = M - 1;
        uint32_t dst = sbase + (uint32_t)(ch >> 2) * 8192 + row * 64
                     + (((uint32_t)((ch & 3) ^ ((row >> 1) & 3))) << 4);
        cpa16(dst, G + (size_t)ga * K + ch * 8);
    }
}

template <int K>
__device__ __forceinline__ void mma_over_K(
    uint32_t as_b, uint32_t bs_b,
    const uint32_t* a_off, const uint32_t* a_sw,
    const uint32_t* b_off, const uint32_t* b_sw,
    uint32_t a_hi, uint32_t b_hi, float acc[4][4][4])
{
    #pragma unroll
    for (int s4 = 0; s4 < K / 32; s4++) {
        #pragma unroll
        for (int s = 0; s < 2; s++) {
            uint32_t afr[4][4];
            #pragma unroll
            for (int mi = 0; mi < 4; mi++)
                ldsm_x4(as_b + s4 * 8192 + a_off[mi]
                        + (((2 * s + a_hi) ^ a_sw[mi]) << 4), afr[mi]);
            uint32_t bfr[2][4];
            #pragma unroll
            for (int p = 0; p < 2; p++)
                ldsm_x4(bs_b + s4 * 8192 + b_off[p]
                        + (((2 * s + b_hi) ^ b_sw[p]) << 4), bfr[p]);
            #pragma unroll
            for (int mi = 0; mi < 4; mi++)
                #pragma unroll
                for (int nj = 0; nj < 4; nj++)
                    mma_f16(acc[mi][nj], afr[mi],
                            &bfr[nj >> 1][(nj & 1) * 2], acc[mi][nj]);
        }
    }
}

#define ACC_ZERO(A_) \
    _Pragma("unroll") \
    for (int i = 0; i < 4; i++) \
        _Pragma("unroll") \
        for (int j = 0; j < 4; j++) \
            _Pragma("unroll") \
            for (int q = 0; q < 4; q++) (A_)[i][j][q] = 0.0f;

#define FRAG_SETUP() \
    const int tid = threadIdx.x; \
    const int warp = tid >> 5; \
    const int lane = tid & 31; \
    const int wm = warp & 1; \
    const int wn = warp >> 1; \
    const int g = lane >> 2; \
    const int tig = lane & 3; \
    const uint32_t a_hi = lane >> 4; \
    const uint32_t b_hi = (lane >> 3) & 1; \
    uint32_t a_off[4], a_sw[4]; \
    _Pragma("unroll") \
    for (int mi = 0; mi < 4; mi++) { \
        int row = wm * 64 + mi * 16 + (lane & 15); \
        a_off[mi] = row * 64; \
        a_sw[mi] = (row >> 1) & 3; \
    } \
    uint32_t b_off[2], b_sw[2]; \
    _Pragma("unroll") \
    for (int p = 0; p < 2; p++) { \
        int row = wn * 32 + p * 16 + (lane & 7) + ((lane >> 4) ? 8 : 0); \
        b_off[p] = row * 64; \
        b_sw[p] = (row >> 1) & 3; \
    } \
    float acc[4][4][4]; \
    ACC_ZERO(acc)

// ---------------------------------------------------------------------------
__global__ void wtrans_all_k(const float* __restrict__ Wxp1, const float* __restrict__ Wxp2,
                             const float* __restrict__ Wep,  const float* __restrict__ Wsl1,
                             const float* __restrict__ Wsl2, const float* __restrict__ Wvl,
                             __half* __restrict__ dst, int ke)
{
    int id = blockIdx.x * 256 + threadIdx.x;
    int s0 = 16384, s1 = 49152, s2 = 384 * ke, s3 = 16384, s4 = 16384, s5 = 16384;
    const float* W; int K, Cc, off, base;
    if (id < s0) { W = Wxp1; K = 128; Cc = 128; base = 0; off = id; }
    else if (id < s0 + s1) { W = Wxp2; K = 128; Cc = 384; base = s0; off = id - s0; }
    else if (id < s0 + s1 + s2) { W = Wep; K = ke; Cc = 384; base = s0 + s1; off = id - s0 - s1; }
    else if (id < s0 + s1 + s2 + s3) { W = Wsl1; K = 128; Cc = 128; base = s0 + s1 + s2; off = id - s0 - s1 - s2; }
    else if (id < s0 + s1 + s2 + s3 + s4) { W = Wsl2; K = 128; Cc = 128; base = s0 + s1 + s2 + s3; off = id - s0 - s1 - s2 - s3; }
    else if (id < s0 + s1 + s2 + s3 + s4 + s5) { W = Wvl; K = 128; Cc = 128; base = s0 + s1 + s2 + s3 + s4; off = id - s0 - s1 - s2 - s3 - s4; }
    else return;
    int k = off % K, c = off / K;
    dst[base + off] = __float2half(W[(size_t)k * Cc + c]);
}

// dual fp32 -> fp16 bulk convert
__global__ void f2h2_k(const float* __restrict__ s1, __half* __restrict__ d1, int n1,
                       const float* __restrict__ s2, __half* __restrict__ d2, int n2)
{
    int i = (blockIdx.x * 256 + threadIdx.x) * 8;
    const float* s; __half* d;
    if (i < n1) { s = s1 + i; d = d1 + i; }
    else if (i < n1 + n2) { s = s2 + (i - n1); d = d2 + (i - n1); }
    else return;
    float4 a = *reinterpret_cast<const float4*>(s);
    float4 b = *reinterpret_cast<const float4*>(s + 4);
    uint4 o = make_uint4(pack_h2(a.x, a.y), pack_h2(a.z, a.w),
                         pack_h2(b.x, b.y), pack_h2(b.z, b.w));
    *reinterpret_cast<uint4*>(d) = o;
}

// 8-rows-per-CTA rowwise GEMM (weight L2 traffic /8)
__global__ void __launch_bounds__(128) rowmm8_k(
    const float* __restrict__ A, const float* __restrict__ W,
    const float* __restrict__ bias, float* __restrict__ C, int ldw)
{
    int r0 = blockIdx.x * 8, f = threadIdx.x;
    __shared__ float a_s[8][128];
    #pragma unroll
    for (int i = 0; i < 8; i++) a_s[i][f] = A[(size_t)(r0 + i) * 128 + f];
    __syncthreads();
    float acc[8];
    float b0 = bias ? bias[f] : 0.0f;
    #pragma unroll
    for (int i = 0; i < 8; i++) acc[i] = b0;
    for (int k = 0; k < 128; k++) {
        float w = W[k * ldw + f];
        #pragma unroll
        for (int i = 0; i < 8; i++) acc[i] += a_s[i][k] * w;
    }
    #pragma unroll
    for (int i = 0; i < 8; i++) C[(size_t)(r0 + i) * 128 + f] = acc[i];
}

// sum_vec[row] = S[row]@Wvl + S[row] + cnt[row/3]*VB[row], 8 rows/CTA
__global__ void __launch_bounds__(128) svecfix8_k(
    const float* __restrict__ S, const float* __restrict__ Wvl,
    const float* __restrict__ VB, const float* __restrict__ cnt,
    float* __restrict__ out)
{
    int r0 = blockIdx.x * 8, f = threadIdx.x;
    __shared__ float a_s[8][128];
    #pragma unroll
    for (int i = 0; i < 8; i++) a_s[i][f] = S[(size_t)(r0 + i) * 128 + f];
    __syncthreads();
    float acc[8];
    #pragma unroll
    for (int i = 0; i < 8; i++) acc[i] = 0.0f;
    for (int k = 0; k < 128; k++) {
        float w = Wvl[k * 128 + f];
        #pragma unroll
        for (int i = 0; i < 8; i++) acc[i] += a_s[i][k] * w;
    }
    #pragma unroll
    for (int i = 0; i < 8; i++) {
        int row = r0 + i;
        out[(size_t)row * 128 + f] = acc[i] + a_s[i][f]
                                   + cnt[row / 3] * VB[(size_t)row * 128 + f];
    }
}

// ---------------------------------------------------------------------------
// pgemm3: t = ssilu(xh@Wxp1+bxp1) (smem, recomputed per slab);
// prod = (t@Wxp2_slab + bxp2)*(edgeh@Wep_slab + bep)*INV3
//   cs<2 : ph[N,256] slab ; cs==2: xnh = fp16(prod + x)
// smem: As 32K | Bs 32K | U(t) 32K
// ---------------------------------------------------------------------------
__global__ void __launch_bounds__(256, 2) pgemm3_k(
    const __half* __restrict__ Xh, const __half* __restrict__ Eh,
    const __half* __restrict__ WTxp1, const __half* __restrict__ WTxp2,
    const __half* __restrict__ WTep,
    const float* __restrict__ bxp1, const float* __restrict__ bxp2,
    const float* __restrict__ bep, const float* __restrict__ x,
    __half* __restrict__ P, __half* __restrict__ Xnh, int M, int ke)
{
    extern __shared__ char dsm[];
    const uint32_t as_b = smem_to_u32(dsm);
    const uint32_t bs_b = as_b + 32768;
    const uint32_t u_b  = as_b + 65536;
    FRAG_SETUP();
    const int row0 = blockIdx.y * 128;
    const int cs = blockIdx.x;
    const int col0 = cs * 128;

    // GEMM0: t = ssilu(xh @ Wxp1 + bxp1)
    load_tile<128>(as_b, Xh, row0, M, tid);
    load_tile<128>(bs_b, WTxp1, 0, 1 << 30, tid);
    CP_COMMIT(); CP_WAIT0();
    __syncthreads();
    mma_over_K<128>(as_b, bs_b, a_off, a_sw, b_off, b_sw, a_hi, b_hi, acc);

    __syncthreads();
    load_tile<128>(bs_b, WTxp2, col0, 1 << 30, tid);
    CP_COMMIT();
    #pragma unroll
    for (int mi = 0; mi < 4; mi++) {
        int rloc = wm * 64 + mi * 16 + g;
        #pragma unroll
        for (int half = 0; half < 2; half++) {
            int rl = rloc + half * 8;
            #pragma unroll
            for (int nj = 0; nj < 4; nj++) {
                int c = wn * 32 + nj * 8 + tig * 2;
                float v0 = ssilu_f(acc[mi][nj][half * 2 + 0] + bxp1[c]);
                float v1 = ssilu_f(acc[mi][nj][half * 2 + 1] + bxp1[c + 1]);
                asm volatile("st.shared.b32 [%0], %1;"
                    :: "r"(u_b + sm_off(rl, c)), "r"(pack_h2(v0, v1)));
            }
        }
    }
    CP_WAIT0();
    __syncthreads();

    // GEMM1: t @ Wxp2 slab
    ACC_ZERO(acc);
    mma_over_K<128>(u_b, bs_b, a_off, a_sw, b_off, b_sw, a_hi, b_hi, acc);

    // GEMM2: edgeh @ Wep slab
    float acc2[4][4][4];
    ACC_ZERO(acc2);
    __syncthreads();
    load_tile<64>(as_b, Eh, row0, M, tid);
    load_tile<64>(bs_b, WTep, col0, 1 << 30, tid);
    CP_COMMIT(); CP_WAIT0();
    __syncthreads();
    mma_over_K<64>(as_b, bs_b, a_off, a_sw, b_off, b_sw, a_hi, b_hi, acc2);

    #pragma unroll
    for (int mi = 0; mi < 4; mi++) {
        int rbase = row0 + wm * 64 + mi * 16 + g;
        #pragma unroll
        for (int half = 0; half < 2; half++) {
            int r = rbase + half * 8;
            if (r >= M) continue;
            #pragma unroll
            for (int nj = 0; nj < 4; nj++) {
                int lc = wn * 32 + nj * 8 + tig * 2;
                int c = col0 + lc;
                float v0 = (acc[mi][nj][half * 2 + 0] + bxp2[c])
                         * (acc2[mi][nj][half * 2 + 0] + bep[c]) * INV3;
                float v1 = (acc[mi][nj][half * 2 + 1] + bxp2[c + 1])
                         * (acc2[mi][nj][half * 2 + 1] + bep[c + 1]) * INV3;
                if (cs < 2) {
                    *reinterpret_cast<uint32_t*>(P + (size_t)r * 256 + c) = pack_h2(v0, v1);
                } else {
                    v0 += x[(size_t)r * 128 + lc];
                    v1 += x[(size_t)r * 128 + lc + 1];
                    *reinterpret_cast<uint32_t*>(Xnh + (size_t)r * 128 + lc) = pack_h2(v0, v1);
                }
            }
        }
    }
}

// ---------------------------------------------------------------------------
// hvec: vecnh @ Wvl + vecnh(from smem) + VB[gather]  (fp32 out)
// ---------------------------------------------------------------------------
__global__ void __launch_bounds__(256, 2) hgemm7_k(
    const __half* __restrict__ A, const __half* __restrict__ WT,
    float* __restrict__ C, int M,
    const float* __restrict__ extra2, const int* __restrict__ bidx)
{
    extern __shared__ char dsm[];
    const uint32_t as_b = smem_to_u32(dsm);
    const uint32_t bs_b = as_b + 32768;
    FRAG_SETUP();
    const int row0 = blockIdx.y * 128;

    load_tile<128>(as_b, A, row0, M, tid);
    load_tile<128>(bs_b, WT, 0, 1 << 30, tid);
    CP_COMMIT(); CP_WAIT0();
    __syncthreads();
    mma_over_K<128>(as_b, bs_b, a_off, a_sw, b_off, b_sw, a_hi, b_hi, acc);

    #pragma unroll
    for (int mi = 0; mi < 4; mi++) {
        int rloc = wm * 64 + mi * 16 + g;
        #pragma unroll
        for (int half = 0; half < 2; half++) {
            int rl = rloc + half * 8;
            int r = row0 + rl;
            if (r >= M) continue;
            int nnode = r / 3;
            size_t e2off = ((size_t)bidx[nnode] * 3 + (r - nnode * 3)) * 128;
            #pragma unroll
            for (int nj = 0; nj < 4; nj++) {
                int c = wn * 32 + nj * 8 + tig * 2;
                uint32_t eh = lds_u32(as_b + sm_off(rl, c));
                __half2 h2 = *reinterpret_cast<__half2*>(&eh);
                C[(size_t)r * 128 + c]     = acc[mi][nj][half * 2 + 0] + __low2float(h2) + extra2[e2off + c];
                C[(size_t)r * 128 + c + 1] = acc[mi][nj][half * 2 + 1] + __high2float(h2) + extra2[e2off + c + 1];
            }
        }
    }
}

// ---------------------------------------------------------------------------
// hx: u = ssilu(xnh@Wsl1 + sB[bidx]); hx = ssilu(u@Wsl2+b2) + xnh(from smem)
// ---------------------------------------------------------------------------
__global__ void __launch_bounds__(256, 2) hgemm2h_k(
    const __half* __restrict__ A, const __half* __restrict__ WT1,
    const __half* __restrict__ WT2,
    const float* __restrict__ sB, const float* __restrict__ bias2,
    const int* __restrict__ bidx, float* __restrict__ C, int M)
{
    extern __shared__ char dsm[];
    const uint32_t as_b = smem_to_u32(dsm);
    const uint32_t bs_b = as_b + 32768;
    const uint32_t u_b  = as_b + 65536;
    FRAG_SETUP();
    const int row0 = blockIdx.y * 128;

    load_tile<128>(as_b, A, row0, M, tid);
    load_tile<128>(bs_b, WT1, 0, 1 << 30, tid);
    CP_COMMIT(); CP_WAIT0();
    __syncthreads();
    mma_over_K<128>(as_b, bs_b, a_off, a_sw, b_off, b_sw, a_hi, b_hi, acc);

    __syncthreads();
    load_tile<128>(bs_b, WT2, 0, 1 << 30, tid);
    CP_COMMIT();

    #pragma unroll
    for (int mi = 0; mi < 4; mi++) {
        int rloc = wm * 64 + mi * 16 + g;
        #pragma unroll
        for (int half = 0; half < 2; half++) {
            int rl = rloc + half * 8;
            int rg = row0 + rl;
            int rr = rg < M ? rg : M - 1;
            int rb = bidx[rr];
            #pragma unroll
            for (int nj = 0; nj < 4; nj++) {
                int c = wn * 32 + nj * 8 + tig * 2;
                float v0 = ssilu_f(acc[mi][nj][half * 2 + 0] + sB[(size_t)rb * 128 + c]);
                float v1 = ssilu_f(acc[mi][nj][half * 2 + 1] + sB[(size_t)rb * 128 + c + 1]);
                asm volatile("st.shared.b32 [%0], %1;"
                    :: "r"(u_b + sm_off(rl, c)), "r"(pack_h2(v0, v1)));
            }
        }
    }
    CP_WAIT0();
    __syncthreads();

    float acc2[4][4][4];
    ACC_ZERO(acc2);
    mma_over_K<128>(u_b, bs_b, a_off, a_sw, b_off, b_sw, a_hi, b_hi, acc2);

    #pragma unroll
    for (int mi = 0; mi < 4; mi++) {
        int rloc = wm * 64 + mi * 16 + g;
        #pragma unroll
        for (int half = 0; half < 2; half++) {
            int rl = rloc + half * 8;
            int r = row0 + rl;
            if (r >= M) continue;
            #pragma unroll
            for (int nj = 0; nj < 4; nj++) {
                int c = wn * 32 + nj * 8 + tig * 2;
                uint32_t xh2 = lds_u32(as_b + sm_off(rl, c));
                __half2 h2 = *reinterpret_cast<__half2*>(&xh2);
                float v0 = ssilu_f(acc2[mi][nj][half * 2 + 0] + bias2[c]) + __low2float(h2);
                float v1 = ssilu_f(acc2[mi][nj][half * 2 + 1] + bias2[c + 1]) + __high2float(h2);
                C[(size_t)r * 128 + c] = v0;
                C[(size_t)r * 128 + c + 1] = v1;
            }
        }
    }
}

// ---------------------------------------------------------------------------
__global__ void node_elem_k(
    const __half* __restrict__ ph, const float* __restrict__ vec,
    const float* __restrict__ ud, __half* __restrict__ vecnh, int N)
{
    int idx = blockIdx.x * blockDim.x + threadIdx.x;
    if (idx >= N * FDIM) return;
    int n = idx >> 7;
    int f = idx & 127;
    size_t b3 = (size_t)n * 384;

    float p1 = __half2float(ph[(size_t)n * 256 + f]);
    float p2 = __half2float(ph[(size_t)n * 256 + 128 + f]);

    float u0 = ud[n * 3 + 0], u1 = ud[n * 3 + 1], u2 = ud[n * 3 + 2];
    float v0 = vec[b3 + 0 * 128 + f];
    float v1 = vec[b3 + 1 * 128 + f];
    float v2 = vec[b3 + 2 * 128 + f];

    vecnh[b3 + 0 * 128 + f] = __float2half((p1 * v0 + p2 * u0) * INVH);
    vecnh[b3 + 1 * 128 + f] = __float2half((p1 * v1 + p2 * u1) * INVH);
    vecnh[b3 + 2 * 128 + f] = __float2half((p1 * v2 + p2 * u2) * INVH);
}

__global__ void zero_k(float* p, int n) {
    int i = blockIdx.x * blockDim.x + threadIdx.x;
    if (i < n) p[i] = 0.0f;
}

__global__ void seg_reduce_cnt_k(const float* src, const int* batch, float* dst,
                                 float* cnt, int N, int rows_per_blk)
{
    int c = threadIdx.x;
    int r0 = blockIdx.x * rows_per_blk;
    if (r0 >= N) return;
    int r1 = min(r0 + rows_per_blk, N);
    int cur = batch[r0];
    float s = 0.0f;
    int runlen = 0;
    for (int r = r0; r < r1; r++) {
        int b = batch[r];
        if (b != cur) {
            atomicAdd(&dst[(size_t)cur * 128 + c], s);
            if (c == 0) atomicAdd(&cnt[cur], (float)runlen);
            s = 0.0f;
            runlen = 0;
            cur = b;
        }
        s += src[(size_t)r * 128 + c];
        runlen++;
    }
    atomicAdd(&dst[(size_t)cur * 128 + c], s);
    if (c == 0) atomicAdd(&cnt[cur], (float)runlen);
}

__global__ void seg_reduce_h_k(const __half* src, const int* batch, float* dst,
                               int N, int rows_per_blk)
{
    int c = threadIdx.x;   // 384
    int r0 = blockIdx.x * rows_per_blk;
    if (r0 >= N) return;
    int r1 = min(r0 + rows_per_blk, N);
    int cur = batch[r0];
    float s = 0.0f;
    for (int r = r0; r < r1; r++) {
        int b = batch[r];
        if (b != cur) {
            atomicAdd(&dst[(size_t)cur * 384 + c], s);
            s = 0.0f;
            cur = b;
        }
        s += __half2float(src[(size_t)r * 384 + c]);
    }
    atomicAdd(&dst[(size_t)cur * 384 + c], s);
}

// ---------------------------------------------------------------------------
__global__ void __launch_bounds__(128) global_k(
    const float* __restrict__ sum_x, const float* __restrict__ sum_vec,
    const float* __restrict__ cnt,
    const float* __restrict__ scalar_l, const float* __restrict__ vector_l,
    const float* __restrict__ W_sg1, const float* __restrict__ b_sg1,
    const float* __restrict__ W_sg2, const float* __restrict__ b_sg2,
    const float* __restrict__ W_vg, const float* __restrict__ W_vp,
    const float* __restrict__ W_lp1, const float* __restrict__ b_lp1,
    const float* __restrict__ W_lp2, const float* __restrict__ b_lp2,
    const float* __restrict__ W_ml,
    float* __restrict__ out_sl, float* __restrict__ out_vl,
    float* __restrict__ out_ld)
{
    int b = blockIdx.x;
    int f = threadIdx.x;
    __shared__ float s_g[256];
    __shared__ float s_t[128];
    __shared__ float s_av[3][128];
    __shared__ float s_vl[3][128];
    __shared__ float s_h1[3][128];
    __shared__ float s_red[12];

    float invc = 1.0f / fmaxf(cnt[b], 1.0f);
    size_t bf = (size_t)b * 128 + f;
    float sclf = scalar_l[bf];
    s_g[f] = sum_x[bf] * invc;
    s_g[128 + f] = sclf;
    float vlg[3];
    #pragma unroll
    for (int d = 0; d < 3; d++) {
        size_t o = (size_t)b * 384 + d * 128 + f;
        vlg[d] = vector_l[o];
        s_av[d][f] = sum_vec[o] * invc + vlg[d];
    }
    __syncthreads();

    float acc = b_sg1[f];
    #pragma unroll 8
    for (int k = 0; k < 256; k++) acc += s_g[k] * W_sg1[k * 128 + f];
    s_t[f] = ssilu_f(acc);
    __syncthreads();

    acc = b_sg2[f];
    #pragma unroll 8
    for (int k = 0; k < 128; k++) acc += s_t[k] * W_sg2[k * 128 + f];
    float sl = sclf + ssilu_f(acc);

    float vl[3];
    #pragma unroll
    for (int d = 0; d < 3; d++) {
        float a = 0.0f;
        #pragma unroll 8
        for (int k = 0; k < 128; k++) a += s_av[d][k] * W_vg[k * 128 + f];
        vl[d] = vlg[d] + a;
        s_vl[d][f] = vl[d];
    }
    __syncthreads();

    float vn = 1e-8f;
    #pragma unroll
    for (int d = 0; d < 3; d++) {
        float h1 = 0.0f, h2 = 0.0f;
        #pragma unroll 8
        for (int k = 0; k < 128; k++) {
            float t = s_vl[d][k];
            h1 += t * W_vp[k * 256 + f];
            h2 += t * W_vp[k * 256 + 128 + f];
        }
        s_h1[d][f] = h1;
        vn += h2 * h2;
    }
    s_g[f] = sl;
    s_g[128 + f] = sqrtf(vn);
    __syncthreads();

    acc = b_lp1[f];
    #pragma unroll 8
    for (int k = 0; k < 256; k++) acc += s_g[k] * W_lp1[k * 128 + f];
    s_t[f] = ssilu_f(acc);
    __syncthreads();

    float s1 = b_lp2[f], s2 = b_lp2[128 + f], s3 = b_lp2[256 + f];
    #pragma unroll 4
    for (int k = 0; k < 128; k++) {
        float t = s_t[k];
        s1 += t * W_lp2[k * 384 + f];
        s2 += t * W_lp2[k * 384 + 128 + f];
        s3 += t * W_lp2[k * 384 + 256 + f];
    }
    out_sl[bf] = s2 + sl * tanhf(s3);

    float wml = W_ml[f];
    float part[3];
    #pragma unroll
    for (int d = 0; d < 3; d++) {
        float v = s1 * s_h1[d][f] + vl[d];
        out_vl[(size_t)b * 384 + d * 128 + f] = v;
        part[d] = v * wml;
    }
    #pragma unroll
    for (int d = 0; d < 3; d++)
        #pragma unroll
        for (int o = 16; o; o >>= 1)
            part[d] += __shfl_down_sync(0xffffffff, part[d], o);
    int w = f >> 5, ln = f & 31;
    if (ln == 0) {
        #pragma unroll
        for (int d = 0; d < 3; d++) s_red[d * 4 + w] = part[d];
    }
    __syncthreads();
    if (f < 3)
        out_ld[b * 3 + f] = s_red[f * 4] + s_red[f * 4 + 1]
                          + s_red[f * 4 + 2] + s_red[f * 4 + 3];
}

// ---------------------------------------------------------------------------
extern "C" void kernel_launch(void* const* d_in, const int* in_sizes, int n_in,
                              void* d_out, int out_size)
{
    const float* x        = (const float*)d_in[0];
    const float* scalar_l = (const float*)d_in[1];
    const float* vec      = (const float*)d_in[2];
    const float* vector_l = (const float*)d_in[3];
    const float* edge_f   = (const float*)d_in[4];
    const float* edge_ud  = (const float*)d_in[5];
    const int*   batch    = (const int*)d_in[6];
    const float* W_sg1 = (const float*)d_in[7];  const float* b_sg1 = (const float*)d_in[8];
    const float* W_sg2 = (const float*)d_in[9];  const float* b_sg2 = (const float*)d_in[10];
    const float* W_sl1 = (const float*)d_in[11]; const float* b_sl1 = (const float*)d_in[12];
    const float* W_sl2 = (const float*)d_in[13]; const float* b_sl2 = (const float*)d_in[14];
    const float* W_vg  = (const float*)d_in[15];
    const float* W_vl  = (const float*)d_in[16];
    const float* W_xp1 = (const float*)d_in[17]; const float* b_xp1 = (const float*)d_in[18];
    const float* W_xp2 = (const float*)d_in[19]; const float* b_xp2 = (const float*)d_in[20];
    const float* W_ep  = (const float*)d_in[21]; const float* b_ep  = (const float*)d_in[22];
    const float* W_vp  = (const float*)d_in[23];
    const float* W_lp1 = (const float*)d_in[24]; const float* b_lp1 = (const float*)d_in[25];
    const float* W_lp2 = (const float*)d_in[26]; const float* b_lp2 = (const float*)d_in[27];
    const float* W_ml  = (const float*)d_in[28];

    const int N = in_sizes[0] / FDIM;
    const int B = in_sizes[1] / FDIM;
    const int ke = in_sizes[4] / N;   // 64

    float* base = nullptr;
    cudaGetSymbolAddress((void**)&base, g_buf);

    const size_t NF = (size_t)N * FDIM;
    const size_t NH = (size_t)N * 128;

    __half* hb    = (__half*)base;
    __half* xnh   = hb;                    // [N,128]
    __half* xh    = hb + NH;               // [N,128]
    __half* vecnh = hb + 2 * NH;           // [3N,128]
    __half* ph    = hb + 5 * NH;           // [N,256]
    __half* edgeh = hb + 7 * NH;           // [N,ke]
    __half* wh    = edgeh + (size_t)N * ke;
    __half* wh_xp1 = wh;
    __half* wh_xp2 = wh + 16384;
    __half* wh_ep  = wh + 65536;
    __half* wh_sl1 = wh + 65536 + 384 * ke;
    __half* wh_sl2 = wh_sl1 + 16384;
    __half* wh_vl  = wh_sl2 + 16384;
    float* smf = (float*)(wh_vl + 16384 + 16);
    float* sum_x   = smf;                        // B*128  (zeroed block start)
    float* S       = sum_x + (size_t)B * 128;    // 3B*128
    float* cnt     = S + (size_t)3 * B * 128;    // B
    float* sB      = cnt + B + 64;               // B*128
    float* VB      = sB + (size_t)B * 128;       // 3B*128
    float* sum_vec = VB + (size_t)3 * B * 128;   // 3B*128

    float* out = (float*)d_out;
    const size_t o0 = 0;
    const size_t o1 = NF;
    const size_t o2 = o1 + 3 * NF;
    const size_t o3 = o2 + (size_t)B * 128;
    const size_t o4 = o3 + (size_t)B * 384;

    const int rT_N  = (N + 127) / 128;
    const int rT_3N = (3 * N + 127) / 128;

    const int GSM = 65536;
    const int GSM3 = 98304;
    cudaFuncSetAttribute(pgemm3_k,  cudaFuncAttributeMaxDynamicSharedMemorySize, GSM3);
    cudaFuncSetAttribute(hgemm7_k,  cudaFuncAttributeMaxDynamicSharedMemorySize, GSM);
    cudaFuncSetAttribute(hgemm2h_k, cudaFuncAttributeMaxDynamicSharedMemorySize, GSM3);

    // 0: all weights -> fp16 transposed
    {
        int tot = 16384 * 4 + 49152 + 384 * ke;
        wtrans_all_k<<<(tot + 255) / 256, 256>>>(W_xp1, W_xp2, W_ep, W_sl1, W_sl2, W_vl, wh, ke);
    }
    // 1: x + edge -> fp16 (single launch)
    {
        int n1 = (int)NH, n2 = N * ke;
        f2h2_k<<<(((n1 + n2) / 8) + 255) / 256, 256>>>(x, xh, n1, edge_f, edgeh, n2);
    }
    // 2: VB = vector_l @ W_vl (8 rows/CTA)
    rowmm8_k<<<(3 * B) / 8, 128>>>(vector_l, W_vl, nullptr, VB, 128);
    // 3: sB = scalar_l @ W_sl1[F:] + b_sl1
    rowmm8_k<<<B / 8, 128>>>(scalar_l, W_sl1 + 128 * 128, b_sl1, sB, 128);
    // 4: fused t + ph slabs 0-1 + xnh (slab 2)
    pgemm3_k<<<dim3(3, rT_N), 256, GSM3>>>(xh, edgeh, wh_xp1, wh_xp2, wh_ep,
                                           b_xp1, b_xp2, b_ep, x, ph, xnh, N, ke);
    // 5: vecnh
    node_elem_k<<<(N * FDIM + 255) / 256, 256>>>(ph, vec, edge_ud, vecnh, N);
    // 6: hx -> out+o0
    hgemm2h_k<<<dim3(1, rT_N), 256, GSM3>>>(xnh, wh_sl1, wh_sl2, sB, b_sl2, batch, out + o0, N);
    // 7: hvec -> out+o1
    hgemm7_k<<<dim3(1, rT_3N), 256, GSM>>>(vecnh, wh_vl, out + o1, 3 * N, VB, batch);
    // 8: zero sum_x | S | cnt
    {
        int nz = B * 128 + 3 * B * 128 + B;
        zero_k<<<(nz + 255) / 256, 256>>>(sum_x, nz);
    }
    // 9: hx -> sum_x, cnt
    seg_reduce_cnt_k<<<(N + 127) / 128, 128>>>(out + o0, batch, sum_x, cnt, N, 128);
    // 10: vecnh -> S
    seg_reduce_h_k<<<(N + 63) / 64, 384>>>(vecnh, batch, S, N, 64);
    // 11: sum_vec = S@Wvl + S + cnt*VB
    svecfix8_k<<<(3 * B) / 8, 128>>>(S, W_vl, VB, cnt, sum_vec);
    // 12: fused global phase
    global_k<<<B, 128>>>(sum_x, sum_vec, cnt, scalar_l, vector_l,
                         W_sg1, b_sg1, W_sg2, b_sg2, W_vg, W_vp,
                         W_lp1, b_lp1, W_lp2, b_lp2, W_ml,
                         out + o2, out + o3, out + o4);
}

// round 15
// speedup vs baseline: 1.0439x; 1.0439x over previous
#include <cuda_runtime.h>
#include <cuda_fp16.h>
#include <math.h>
#include <stdint.h>

#define FDIM 128
#define SSCALE 1.6666666666666667f   // 1/0.6
#define INV3 0.5773502691896258f     // 1/sqrt(3)
#define INVH 0.08838834764831845f    // 1/sqrt(128)

static __device__ float g_buf[127000000];

__device__ __forceinline__ float ssilu_f(float v) {
    return v * SSCALE / (1.0f + __expf(-v));
}

__device__ __forceinline__ uint32_t pack_h2(float a, float b) {
    __half2 h = __floats2half2_rn(a, b);
    return *reinterpret_cast<uint32_t*>(&h);
}

__device__ __forceinline__ uint32_t smem_to_u32(const void* smem_ptr) {
    uint32_t addr;
    asm("{ .reg .u64 tmp; cvta.to.shared.u64 tmp, %1; cvt.u32.u64 %0, tmp; }"
        : "=r"(addr) : "l"(smem_ptr));
    return addr;
}

__device__ __forceinline__ void ldsm_x4(uint32_t addr, uint32_t* r) {
    asm volatile("ldmatrix.sync.aligned.m8n8.x4.shared.b16 {%0,%1,%2,%3}, [%4];"
        : "=r"(r[0]), "=r"(r[1]), "=r"(r[2]), "=r"(r[3]) : "r"(addr));
}

__device__ __forceinline__ uint32_t lds_u32(uint32_t addr) {
    uint32_t v;
    asm volatile("ld.shared.b32 %0, [%1];" : "=r"(v) : "r"(addr));
    return v;
}

__device__ __forceinline__ void mma_f16(float* d, const uint32_t* a,
                                        const uint32_t* b, const float* c) {
    asm volatile(
        "mma.sync.aligned.m16n8k16.row.col.f32.f16.f16.f32 "
        "{%0,%1,%2,%3},{%4,%5,%6,%7},{%8,%9},{%10,%11,%12,%13};"
        : "=f"(d[0]), "=f"(d[1]), "=f"(d[2]), "=f"(d[3])
        : "r"(a[0]), "r"(a[1]), "r"(a[2]), "r"(a[3]),
          "r"(b[0]), "r"(b[1]),
          "f"(c[0]), "f"(c[1]), "f"(c[2]), "f"(c[3]));
}

__device__ __forceinline__ void cpa16(uint32_t dst, const void* src) {
    asm volatile("cp.async.cg.shared.global [%0], [%1], 16;" :: "r"(dst), "l"(src));
}
#define CP_COMMIT() asm volatile("cp.async.commit_group;" ::: "memory")
#define CP_WAIT0()  asm volatile("cp.async.wait_group 0;" ::: "memory")

__device__ __forceinline__ uint32_t sm_off(int row, int c) {
    uint32_t chunk = (uint32_t)(c & 31) >> 3;
    return (uint32_t)(c >> 5) * 8192 + row * 64
         + ((chunk ^ ((uint32_t)(row >> 1) & 3)) << 4) + ((c & 7) * 2);
}

template <int K>
__device__ __forceinline__ void load_tile(uint32_t sbase, const __half* G,
                                          int grow0, int M, int tid)
{
    constexpr int NCH = K / 8;
    #pragma unroll
    for (int t = 0; t < (128 * NCH) / 256; t++) {
        int id = tid + t * 256;
        int row = id / NCH;
        int ch = id % NCH;
        int ga = grow0 + row;
        if (ga >= M) ga = M - 1;
        uint32_t dst = sbase + (uint32_t)(ch >> 2) * 8192 + row * 64
                     + (((uint32_t)((ch & 3) ^ ((row >> 1) & 3))) << 4);
        cpa16(dst, G + (size_t)ga * K + ch * 8);
    }
}

template <int K>
__device__ __forceinline__ void mma_over_K(
    uint32_t as_b, uint32_t bs_b,
    const uint32_t* a_off, const uint32_t* a_sw,
    const uint32_t* b_off, const uint32_t* b_sw,
    uint32_t a_hi, uint32_t b_hi, float acc[4][4][4])
{
    #pragma unroll
    for (int s4 = 0; s4 < K / 32; s4++) {
        #pragma unroll
        for (int s = 0; s < 2; s++) {
            uint32_t afr[4][4];
            #pragma unroll
            for (int mi = 0; mi < 4; mi++)
                ldsm_x4(as_b + s4 * 8192 + a_off[mi]
                        + (((2 * s + a_hi) ^ a_sw[mi]) << 4), afr[mi]);
            uint32_t bfr[2][4];
            #pragma unroll
            for (int p = 0; p < 2; p++)
                ldsm_x4(bs_b + s4 * 8192 + b_off[p]
                        + (((2 * s + b_hi) ^ b_sw[p]) << 4), bfr[p]);
            #pragma unroll
            for (int mi = 0; mi < 4; mi++)
                #pragma unroll
                for (int nj = 0; nj < 4; nj++)
                    mma_f16(acc[mi][nj], afr[mi],
                            &bfr[nj >> 1][(nj & 1) * 2], acc[mi][nj]);
        }
    }
}

#define ACC_ZERO(A_) \
    _Pragma("unroll") \
    for (int i = 0; i < 4; i++) \
        _Pragma("unroll") \
        for (int j = 0; j < 4; j++) \
            _Pragma("unroll") \
            for (int q = 0; q < 4; q++) (A_)[i][j][q] = 0.0f;

#define FRAG_SETUP() \
    const int tid = threadIdx.x; \
    const int warp = tid >> 5; \
    const int lane = tid & 31; \
    const int wm = warp & 1; \
    const int wn = warp >> 1; \
    const int g = lane >> 2; \
    const int tig = lane & 3; \
    const uint32_t a_hi = lane >> 4; \
    const uint32_t b_hi = (lane >> 3) & 1; \
    uint32_t a_off[4], a_sw[4]; \
    _Pragma("unroll") \
    for (int mi = 0; mi < 4; mi++) { \
        int row = wm * 64 + mi * 16 + (lane & 15); \
        a_off[mi] = row * 64; \
        a_sw[mi] = (row >> 1) & 3; \
    } \
    uint32_t b_off[2], b_sw[2]; \
    _Pragma("unroll") \
    for (int p = 0; p < 2; p++) { \
        int row = wn * 32 + p * 16 + (lane & 7) + ((lane >> 4) ? 8 : 0); \
        b_off[p] = row * 64; \
        b_sw[p] = (row >> 1) & 3; \
    } \
    float acc[4][4][4]; \
    ACC_ZERO(acc)

// ---------------------------------------------------------------------------
__global__ void wtrans_all_k(const float* __restrict__ Wxp1, const float* __restrict__ Wxp2,
                             const float* __restrict__ Wep,  const float* __restrict__ Wsl1,
                             const float* __restrict__ Wsl2, const float* __restrict__ Wvl,
                             __half* __restrict__ dst, int ke)
{
    int id = blockIdx.x * 256 + threadIdx.x;
    int s0 = 16384, s1 = 49152, s2 = 384 * ke, s3 = 16384, s4 = 16384, s5 = 16384;
    const float* W; int K, Cc, off, base;
    if (id < s0) { W = Wxp1; K = 128; Cc = 128; base = 0; off = id; }
    else if (id < s0 + s1) { W = Wxp2; K = 128; Cc = 384; base = s0; off = id - s0; }
    else if (id < s0 + s1 + s2) { W = Wep; K = ke; Cc = 384; base = s0 + s1; off = id - s0 - s1; }
    else if (id < s0 + s1 + s2 + s3) { W = Wsl1; K = 128; Cc = 128; base = s0 + s1 + s2; off = id - s0 - s1 - s2; }
    else if (id < s0 + s1 + s2 + s3 + s4) { W = Wsl2; K = 128; Cc = 128; base = s0 + s1 + s2 + s3; off = id - s0 - s1 - s2 - s3; }
    else if (id < s0 + s1 + s2 + s3 + s4 + s5) { W = Wvl; K = 128; Cc = 128; base = s0 + s1 + s2 + s3 + s4; off = id - s0 - s1 - s2 - s3 - s4; }
    else return;
    int k = off % K, c = off / K;
    dst[base + off] = __float2half(W[(size_t)k * Cc + c]);
}

// dual fp32 -> fp16 bulk convert (one launch)
__global__ void f2h2_k(const float* __restrict__ s1, __half* __restrict__ d1, int n1,
                       const float* __restrict__ s2, __half* __restrict__ d2, int n2)
{
    int i = (blockIdx.x * 256 + threadIdx.x) * 8;
    const float* s; __half* d;
    if (i < n1) { s = s1 + i; d = d1 + i; }
    else if (i < n1 + n2) { s = s2 + (i - n1); d = d2 + (i - n1); }
    else return;
    float4 a = *reinterpret_cast<const float4*>(s);
    float4 b = *reinterpret_cast<const float4*>(s + 4);
    uint4 o = make_uint4(pack_h2(a.x, a.y), pack_h2(a.z, a.w),
                         pack_h2(b.x, b.y), pack_h2(b.z, b.w));
    *reinterpret_cast<uint4*>(d) = o;
}

// 1 row/CTA rowwise GEMM (proven in R13)
__global__ void __launch_bounds__(128) rowmm_k(
    const float* __restrict__ A, const float* __restrict__ W,
    const float* __restrict__ bias, float* __restrict__ C, int ldw)
{
    int row = blockIdx.x, f = threadIdx.x;
    __shared__ float a_s[128];
    a_s[f] = A[(size_t)row * 128 + f];
    __syncthreads();
    float acc = bias ? bias[f] : 0.0f;
    #pragma unroll 8
    for (int k = 0; k < 128; k++) acc += a_s[k] * W[k * ldw + f];
    C[(size_t)row * 128 + f] = acc;
}

// 4 rows/CTA variant for VB (1536 rows -> 384 CTAs; weight reuse x4)
__global__ void __launch_bounds__(128) rowmm4_k(
    const float* __restrict__ A, const float* __restrict__ W,
    float* __restrict__ C, int ldw)
{
    int r0 = blockIdx.x * 4, f = threadIdx.x;
    __shared__ float a_s[4][128];
    #pragma unroll
    for (int i = 0; i < 4; i++) a_s[i][f] = A[(size_t)(r0 + i) * 128 + f];
    __syncthreads();
    float acc[4] = {0.f, 0.f, 0.f, 0.f};
    for (int k = 0; k < 128; k++) {
        float w = W[k * ldw + f];
        #pragma unroll
        for (int i = 0; i < 4; i++) acc[i] += a_s[i][k] * w;
    }
    #pragma unroll
    for (int i = 0; i < 4; i++) C[(size_t)(r0 + i) * 128 + f] = acc[i];
}

__global__ void __launch_bounds__(128) svecfix_k(
    const float* __restrict__ S, const float* __restrict__ Wvl,
    const float* __restrict__ VB, const float* __restrict__ cnt,
    float* __restrict__ out)
{
    int row = blockIdx.x, f = threadIdx.x;
    int b = row / 3;
    __shared__ float a_s[128];
    a_s[f] = S[(size_t)row * 128 + f];
    __syncthreads();
    float acc = 0.0f;
    #pragma unroll 8
    for (int k = 0; k < 128; k++) acc += a_s[k] * Wvl[k * 128 + f];
    out[(size_t)row * 128 + f] = acc + a_s[f] + cnt[b] * VB[(size_t)row * 128 + f];
}

// ---------------------------------------------------------------------------
// th = ssilu(xh @ Wxp1 + b)  (fp16 out)
// ---------------------------------------------------------------------------
__global__ void __launch_bounds__(256, 2) hgemm_e2_k(
    const __half* __restrict__ A, const __half* __restrict__ WT,
    const float* __restrict__ bias, __half* __restrict__ C, int M)
{
    extern __shared__ char dsm[];
    const uint32_t as_b = smem_to_u32(dsm);
    const uint32_t bs_b = as_b + 32768;
    FRAG_SETUP();
    const int row0 = blockIdx.y * 128;

    load_tile<128>(as_b, A, row0, M, tid);
    load_tile<128>(bs_b, WT, 0, 1 << 30, tid);
    CP_COMMIT(); CP_WAIT0();
    __syncthreads();
    mma_over_K<128>(as_b, bs_b, a_off, a_sw, b_off, b_sw, a_hi, b_hi, acc);

    #pragma unroll
    for (int mi = 0; mi < 4; mi++) {
        int rbase = row0 + wm * 64 + mi * 16 + g;
        #pragma unroll
        for (int half = 0; half < 2; half++) {
            int r = rbase + half * 8;
            if (r >= M) continue;
            #pragma unroll
            for (int nj = 0; nj < 4; nj++) {
                int c = wn * 32 + nj * 8 + tig * 2;
                float v0 = ssilu_f(acc[mi][nj][half * 2 + 0] + bias[c]);
                float v1 = ssilu_f(acc[mi][nj][half * 2 + 1] + bias[c + 1]);
                *reinterpret_cast<uint32_t*>(C + (size_t)r * 128 + c) = pack_h2(v0, v1);
            }
        }
    }
}

// ---------------------------------------------------------------------------
// pgemm: prod = (th@Wxp2+bxp2)*(edgeh@Wep+bep)*INV3
//   cs<2 : ph[N,256] slab ; cs==2: xnh = fp16(prod + x)
// ---------------------------------------------------------------------------
__global__ void __launch_bounds__(256, 2) pgemm_k(
    const __half* __restrict__ Th, const __half* __restrict__ Eh,
    const __half* __restrict__ WTxp2, const __half* __restrict__ WTep,
    const float* __restrict__ bxp2, const float* __restrict__ bep,
    const float* __restrict__ x,
    __half* __restrict__ P, __half* __restrict__ Xnh, int M, int ke)
{
    extern __shared__ char dsm[];
    const uint32_t as_b = smem_to_u32(dsm);
    const uint32_t bs_b = as_b + 32768;
    FRAG_SETUP();
    const int row0 = blockIdx.y * 128;
    const int cs = blockIdx.x;
    const int col0 = cs * 128;

    load_tile<128>(as_b, Th, row0, M, tid);
    load_tile<128>(bs_b, WTxp2, col0, 1 << 30, tid);
    CP_COMMIT(); CP_WAIT0();
    __syncthreads();
    mma_over_K<128>(as_b, bs_b, a_off, a_sw, b_off, b_sw, a_hi, b_hi, acc);

    float acc2[4][4][4];
    ACC_ZERO(acc2);

    __syncthreads();
    load_tile<64>(as_b, Eh, row0, M, tid);
    load_tile<64>(bs_b, WTep, col0, 1 << 30, tid);
    CP_COMMIT(); CP_WAIT0();
    __syncthreads();
    mma_over_K<64>(as_b, bs_b, a_off, a_sw, b_off, b_sw, a_hi, b_hi, acc2);

    #pragma unroll
    for (int mi = 0; mi < 4; mi++) {
        int rbase = row0 + wm * 64 + mi * 16 + g;
        #pragma unroll
        for (int half = 0; half < 2; half++) {
            int r = rbase + half * 8;
            if (r >= M) continue;
            #pragma unroll
            for (int nj = 0; nj < 4; nj++) {
                int lc = wn * 32 + nj * 8 + tig * 2;
                int c = col0 + lc;
                float v0 = (acc[mi][nj][half * 2 + 0] + bxp2[c])
                         * (acc2[mi][nj][half * 2 + 0] + bep[c]) * INV3;
                float v1 = (acc[mi][nj][half * 2 + 1] + bxp2[c + 1])
                         * (acc2[mi][nj][half * 2 + 1] + bep[c + 1]) * INV3;
                if (cs < 2) {
                    *reinterpret_cast<uint32_t*>(P + (size_t)r * 256 + c) = pack_h2(v0, v1);
                } else {
                    v0 += x[(size_t)r * 128 + lc];
                    v1 += x[(size_t)r * 128 + lc + 1];
                    *reinterpret_cast<uint32_t*>(Xnh + (size_t)r * 128 + lc) = pack_h2(v0, v1);
                }
            }
        }
    }
}

// ---------------------------------------------------------------------------
// hvec: vecnh @ Wvl + vecnh(from smem) + VB[gather]  (fp32 out)
// ---------------------------------------------------------------------------
__global__ void __launch_bounds__(256, 2) hgemm7_k(
    const __half* __restrict__ A, const __half* __restrict__ WT,
    float* __restrict__ C, int M,
    const float* __restrict__ extra2, const int* __restrict__ bidx)
{
    extern __shared__ char dsm[];
    const uint32_t as_b = smem_to_u32(dsm);
    const uint32_t bs_b = as_b + 32768;
    FRAG_SETUP();
    const int row0 = blockIdx.y * 128;

    load_tile<128>(as_b, A, row0, M, tid);
    load_tile<128>(bs_b, WT, 0, 1 << 30, tid);
    CP_COMMIT(); CP_WAIT0();
    __syncthreads();
    mma_over_K<128>(as_b, bs_b, a_off, a_sw, b_off, b_sw, a_hi, b_hi, acc);

    #pragma unroll
    for (int mi = 0; mi < 4; mi++) {
        int rloc = wm * 64 + mi * 16 + g;
        #pragma unroll
        for (int half = 0; half < 2; half++) {
            int rl = rloc + half * 8;
            int r = row0 + rl;
            if (r >= M) continue;
            int nnode = r / 3;
            size_t e2off = ((size_t)bidx[nnode] * 3 + (r - nnode * 3)) * 128;
            #pragma unroll
            for (int nj = 0; nj < 4; nj++) {
                int c = wn * 32 + nj * 8 + tig * 2;
                uint32_t eh = lds_u32(as_b + sm_off(rl, c));
                __half2 h2 = *reinterpret_cast<__half2*>(&eh);
                C[(size_t)r * 128 + c]     = acc[mi][nj][half * 2 + 0] + __low2float(h2) + extra2[e2off + c];
                C[(size_t)r * 128 + c + 1] = acc[mi][nj][half * 2 + 1] + __high2float(h2) + extra2[e2off + c + 1];
            }
        }
    }
}

// ---------------------------------------------------------------------------
// hx: u = ssilu(xnh@Wsl1 + sB[bidx]); hx = ssilu(u@Wsl2+b2) + xnh(from smem)
// ---------------------------------------------------------------------------
__global__ void __launch_bounds__(256, 2) hgemm2h_k(
    const __half* __restrict__ A, const __half* __restrict__ WT1,
    const __half* __restrict__ WT2,
    const float* __restrict__ sB, const float* __restrict__ bias2,
    const int* __restrict__ bidx, float* __restrict__ C, int M)
{
    extern __shared__ char dsm[];
    const uint32_t as_b = smem_to_u32(dsm);
    const uint32_t bs_b = as_b + 32768;
    const uint32_t u_b  = as_b + 65536;
    FRAG_SETUP();
    const int row0 = blockIdx.y * 128;

    load_tile<128>(as_b, A, row0, M, tid);
    load_tile<128>(bs_b, WT1, 0, 1 << 30, tid);
    CP_COMMIT(); CP_WAIT0();
    __syncthreads();
    mma_over_K<128>(as_b, bs_b, a_off, a_sw, b_off, b_sw, a_hi, b_hi, acc);

    __syncthreads();
    load_tile<128>(bs_b, WT2, 0, 1 << 30, tid);
    CP_COMMIT();

    #pragma unroll
    for (int mi = 0; mi < 4; mi++) {
        int rloc = wm * 64 + mi * 16 + g;
        #pragma unroll
        for (int half = 0; half < 2; half++) {
            int rl = rloc + half * 8;
            int rg = row0 + rl;
            int rr = rg < M ? rg : M - 1;
            int rb = bidx[rr];
            #pragma unroll
            for (int nj = 0; nj < 4; nj++) {
                int c = wn * 32 + nj * 8 + tig * 2;
                float v0 = ssilu_f(acc[mi][nj][half * 2 + 0] + sB[(size_t)rb * 128 + c]);
                float v1 = ssilu_f(acc[mi][nj][half * 2 + 1] + sB[(size_t)rb * 128 + c + 1]);
                asm volatile("st.shared.b32 [%0], %1;"
                    :: "r"(u_b + sm_off(rl, c)), "r"(pack_h2(v0, v1)));
            }
        }
    }
    CP_WAIT0();
    __syncthreads();

    float acc2[4][4][4];
    ACC_ZERO(acc2);
    mma_over_K<128>(u_b, bs_b, a_off, a_sw, b_off, b_sw, a_hi, b_hi, acc2);

    #pragma unroll
    for (int mi = 0; mi < 4; mi++) {
        int rloc = wm * 64 + mi * 16 + g;
        #pragma unroll
        for (int half = 0; half < 2; half++) {
            int rl = rloc + half * 8;
            int r = row0 + rl;
            if (r >= M) continue;
            #pragma unroll
            for (int nj = 0; nj < 4; nj++) {
                int c = wn * 32 + nj * 8 + tig * 2;
                uint32_t xh2 = lds_u32(as_b + sm_off(rl, c));
                __half2 h2 = *reinterpret_cast<__half2*>(&xh2);
                float v0 = ssilu_f(acc2[mi][nj][half * 2 + 0] + bias2[c]) + __low2float(h2);
                float v1 = ssilu_f(acc2[mi][nj][half * 2 + 1] + bias2[c + 1]) + __high2float(h2);
                C[(size_t)r * 128 + c] = v0;
                C[(size_t)r * 128 + c + 1] = v1;
            }
        }
    }
}

// ---------------------------------------------------------------------------
__global__ void node_elem_k(
    const __half* __restrict__ ph, const float* __restrict__ vec,
    const float* __restrict__ ud, __half* __restrict__ vecnh, int N)
{
    int idx = blockIdx.x * blockDim.x + threadIdx.x;
    if (idx >= N * FDIM) return;
    int n = idx >> 7;
    int f = idx & 127;
    size_t b3 = (size_t)n * 384;

    float p1 = __half2float(ph[(size_t)n * 256 + f]);
    float p2 = __half2float(ph[(size_t)n * 256 + 128 + f]);

    float u0 = ud[n * 3 + 0], u1 = ud[n * 3 + 1], u2 = ud[n * 3 + 2];
    float v0 = vec[b3 + 0 * 128 + f];
    float v1 = vec[b3 + 1 * 128 + f];
    float v2 = vec[b3 + 2 * 128 + f];

    vecnh[b3 + 0 * 128 + f] = __float2half((p1 * v0 + p2 * u0) * INVH);
    vecnh[b3 + 1 * 128 + f] = __float2half((p1 * v1 + p2 * u1) * INVH);
    vecnh[b3 + 2 * 128 + f] = __float2half((p1 * v2 + p2 * u2) * INVH);
}

__global__ void zero_k(float* p, int n) {
    int i = blockIdx.x * blockDim.x + threadIdx.x;
    if (i < n) p[i] = 0.0f;
}

__global__ void seg_reduce_cnt_k(const float* src, const int* batch, float* dst,
                                 float* cnt, int N, int rows_per_blk)
{
    int c = threadIdx.x;
    int r0 = blockIdx.x * rows_per_blk;
    if (r0 >= N) return;
    int r1 = min(r0 + rows_per_blk, N);
    int cur = batch[r0];
    float s = 0.0f;
    int runlen = 0;
    for (int r = r0; r < r1; r++) {
        int b = batch[r];
        if (b != cur) {
            atomicAdd(&dst[(size_t)cur * 128 + c], s);
            if (c == 0) atomicAdd(&cnt[cur], (float)runlen);
            s = 0.0f;
            runlen = 0;
            cur = b;
        }
        s += src[(size_t)r * 128 + c];
        runlen++;
    }
    atomicAdd(&dst[(size_t)cur * 128 + c], s);
    if (c == 0) atomicAdd(&cnt[cur], (float)runlen);
}

__global__ void seg_reduce_h_k(const __half* src, const int* batch, float* dst,
                               int N, int rows_per_blk)
{
    int c = threadIdx.x;   // 384
    int r0 = blockIdx.x * rows_per_blk;
    if (r0 >= N) return;
    int r1 = min(r0 + rows_per_blk, N);
    int cur = batch[r0];
    float s = 0.0f;
    for (int r = r0; r < r1; r++) {
        int b = batch[r];
        if (b != cur) {
            atomicAdd(&dst[(size_t)cur * 384 + c], s);
            s = 0.0f;
            cur = b;
        }
        s += __half2float(src[(size_t)r * 384 + c]);
    }
    atomicAdd(&dst[(size_t)cur * 384 + c], s);
}

// ---------------------------------------------------------------------------
__global__ void __launch_bounds__(128) global_k(
    const float* __restrict__ sum_x, const float* __restrict__ sum_vec,
    const float* __restrict__ cnt,
    const float* __restrict__ scalar_l, const float* __restrict__ vector_l,
    const float* __restrict__ W_sg1, const float* __restrict__ b_sg1,
    const float* __restrict__ W_sg2, const float* __restrict__ b_sg2,
    const float* __restrict__ W_vg, const float* __restrict__ W_vp,
    const float* __restrict__ W_lp1, const float* __restrict__ b_lp1,
    const float* __restrict__ W_lp2, const float* __restrict__ b_lp2,
    const float* __restrict__ W_ml,
    float* __restrict__ out_sl, float* __restrict__ out_vl,
    float* __restrict__ out_ld)
{
    int b = blockIdx.x;
    int f = threadIdx.x;
    __shared__ float s_g[256];
    __shared__ float s_t[128];
    __shared__ float s_av[3][128];
    __shared__ float s_vl[3][128];
    __shared__ float s_h1[3][128];
    __shared__ float s_red[12];

    float invc = 1.0f / fmaxf(cnt[b], 1.0f);
    size_t bf = (size_t)b * 128 + f;
    float sclf = scalar_l[bf];
    s_g[f] = sum_x[bf] * invc;
    s_g[128 + f] = sclf;
    float vlg[3];
    #pragma unroll
    for (int d = 0; d < 3; d++) {
        size_t o = (size_t)b * 384 + d * 128 + f;
        vlg[d] = vector_l[o];
        s_av[d][f] = sum_vec[o] * invc + vlg[d];
    }
    __syncthreads();

    float acc = b_sg1[f];
    #pragma unroll 8
    for (int k = 0; k < 256; k++) acc += s_g[k] * W_sg1[k * 128 + f];
    s_t[f] = ssilu_f(acc);
    __syncthreads();

    acc = b_sg2[f];
    #pragma unroll 8
    for (int k = 0; k < 128; k++) acc += s_t[k] * W_sg2[k * 128 + f];
    float sl = sclf + ssilu_f(acc);

    float vl[3];
    #pragma unroll
    for (int d = 0; d < 3; d++) {
        float a = 0.0f;
        #pragma unroll 8
        for (int k = 0; k < 128; k++) a += s_av[d][k] * W_vg[k * 128 + f];
        vl[d] = vlg[d] + a;
        s_vl[d][f] = vl[d];
    }
    __syncthreads();

    float vn = 1e-8f;
    #pragma unroll
    for (int d = 0; d < 3; d++) {
        float h1 = 0.0f, h2 = 0.0f;
        #pragma unroll 8
        for (int k = 0; k < 128; k++) {
            float t = s_vl[d][k];
            h1 += t * W_vp[k * 256 + f];
            h2 += t * W_vp[k * 256 + 128 + f];
        }
        s_h1[d][f] = h1;
        vn += h2 * h2;
    }
    s_g[f] = sl;
    s_g[128 + f] = sqrtf(vn);
    __syncthreads();

    acc = b_lp1[f];
    #pragma unroll 8
    for (int k = 0; k < 256; k++) acc += s_g[k] * W_lp1[k * 128 + f];
    s_t[f] = ssilu_f(acc);
    __syncthreads();

    float s1 = b_lp2[f], s2 = b_lp2[128 + f], s3 = b_lp2[256 + f];
    #pragma unroll 4
    for (int k = 0; k < 128; k++) {
        float t = s_t[k];
        s1 += t * W_lp2[k * 384 + f];
        s2 += t * W_lp2[k * 384 + 128 + f];
        s3 += t * W_lp2[k * 384 + 256 + f];
    }
    out_sl[bf] = s2 + sl * tanhf(s3);

    float wml = W_ml[f];
    float part[3];
    #pragma unroll
    for (int d = 0; d < 3; d++) {
        float v = s1 * s_h1[d][f] + vl[d];
        out_vl[(size_t)b * 384 + d * 128 + f] = v;
        part[d] = v * wml;
    }
    #pragma unroll
    for (int d = 0; d < 3; d++)
        #pragma unroll
        for (int o = 16; o; o >>= 1)
            part[d] += __shfl_down_sync(0xffffffff, part[d], o);
    int w = f >> 5, ln = f & 31;
    if (ln == 0) {
        #pragma unroll
        for (int d = 0; d < 3; d++) s_red[d * 4 + w] = part[d];
    }
    __syncthreads();
    if (f < 3)
        out_ld[b * 3 + f] = s_red[f * 4] + s_red[f * 4 + 1]
                          + s_red[f * 4 + 2] + s_red[f * 4 + 3];
}

// ---------------------------------------------------------------------------
extern "C" void kernel_launch(void* const* d_in, const int* in_sizes, int n_in,
                              void* d_out, int out_size)
{
    const float* x        = (const float*)d_in[0];
    const float* scalar_l = (const float*)d_in[1];
    const float* vec      = (const float*)d_in[2];
    const float* vector_l = (const float*)d_in[3];
    const float* edge_f   = (const float*)d_in[4];
    const float* edge_ud  = (const float*)d_in[5];
    const int*   batch    = (const int*)d_in[6];
    const float* W_sg1 = (const float*)d_in[7];  const float* b_sg1 = (const float*)d_in[8];
    const float* W_sg2 = (const float*)d_in[9];  const float* b_sg2 = (const float*)d_in[10];
    const float* W_sl1 = (const float*)d_in[11]; const float* b_sl1 = (const float*)d_in[12];
    const float* W_sl2 = (const float*)d_in[13]; const float* b_sl2 = (const float*)d_in[14];
    const float* W_vg  = (const float*)d_in[15];
    const float* W_vl  = (const float*)d_in[16];
    const float* W_xp1 = (const float*)d_in[17]; const float* b_xp1 = (const float*)d_in[18];
    const float* W_xp2 = (const float*)d_in[19]; const float* b_xp2 = (const float*)d_in[20];
    const float* W_ep  = (const float*)d_in[21]; const float* b_ep  = (const float*)d_in[22];
    const float* W_vp  = (const float*)d_in[23];
    const float* W_lp1 = (const float*)d_in[24]; const float* b_lp1 = (const float*)d_in[25];
    const float* W_lp2 = (const float*)d_in[26]; const float* b_lp2 = (const float*)d_in[27];
    const float* W_ml  = (const float*)d_in[28];

    const int N = in_sizes[0] / FDIM;
    const int B = in_sizes[1] / FDIM;
    const int ke = in_sizes[4] / N;   // 64

    float* base = nullptr;
    cudaGetSymbolAddress((void**)&base, g_buf);

    const size_t NF = (size_t)N * FDIM;
    const size_t NH = (size_t)N * 128;

    __half* hb    = (__half*)base;
    __half* th    = hb;                    // [N,128]
    __half* xnh   = hb + NH;               // [N,128]
    __half* xh    = hb + 2 * NH;           // [N,128]
    __half* vecnh = hb + 3 * NH;           // [3N,128]
    __half* ph    = hb + 6 * NH;           // [N,256]
    __half* edgeh = hb + 8 * NH;           // [N,ke]
    __half* wh    = edgeh + (size_t)N * ke;
    __half* wh_xp1 = wh;
    __half* wh_xp2 = wh + 16384;
    __half* wh_ep  = wh + 65536;
    __half* wh_sl1 = wh + 65536 + 384 * ke;
    __half* wh_sl2 = wh_sl1 + 16384;
    __half* wh_vl  = wh_sl2 + 16384;
    float* smf = (float*)(wh_vl + 16384 + 16);
    float* sum_x   = smf;                        // B*128  (zeroed block start)
    float* S       = sum_x + (size_t)B * 128;    // 3B*128
    float* cnt     = S + (size_t)3 * B * 128;    // B
    float* sB      = cnt + B + 64;               // B*128
    float* VB      = sB + (size_t)B * 128;       // 3B*128
    float* sum_vec = VB + (size_t)3 * B * 128;   // 3B*128

    float* out = (float*)d_out;
    const size_t o0 = 0;
    const size_t o1 = NF;
    const size_t o2 = o1 + 3 * NF;
    const size_t o3 = o2 + (size_t)B * 128;
    const size_t o4 = o3 + (size_t)B * 384;

    const int rT_N  = (N + 127) / 128;
    const int rT_3N = (3 * N + 127) / 128;

    const int GSM = 65536;
    const int GSM3 = 98304;
    cudaFuncSetAttribute(hgemm_e2_k, cudaFuncAttributeMaxDynamicSharedMemorySize, GSM);
    cudaFuncSetAttribute(pgemm_k,    cudaFuncAttributeMaxDynamicSharedMemorySize, GSM);
    cudaFuncSetAttribute(hgemm7_k,   cudaFuncAttributeMaxDynamicSharedMemorySize, GSM);
    cudaFuncSetAttribute(hgemm2h_k,  cudaFuncAttributeMaxDynamicSharedMemorySize, GSM3);

    // 0: all weights -> fp16 transposed
    {
        int tot = 16384 * 4 + 49152 + 384 * ke;
        wtrans_all_k<<<(tot + 255) / 256, 256>>>(W_xp1, W_xp2, W_ep, W_sl1, W_sl2, W_vl, wh, ke);
    }
    // 1: x + edge -> fp16 (single launch)
    {
        int n1 = (int)NH, n2 = N * ke;
        f2h2_k<<<(((n1 + n2) / 8) + 255) / 256, 256>>>(x, xh, n1, edge_f, edgeh, n2);
    }
    // 2: VB = vector_l @ W_vl (4 rows/CTA: 384 CTAs)
    rowmm4_k<<<(3 * B) / 4, 128>>>(vector_l, W_vl, VB, 128);
    // 3: sB = scalar_l @ W_sl1[F:] + b_sl1 (1 row/CTA, proven)
    rowmm_k<<<B, 128>>>(scalar_l, W_sl1 + 128 * 128, b_sl1, sB, 128);
    // 4: th = ssilu(xh @ W_xp1 + b_xp1)
    hgemm_e2_k<<<dim3(1, rT_N), 256, GSM>>>(xh, wh_xp1, b_xp1, th, N);
    // 5: ph slabs 0-1, xnh from slab 2
    pgemm_k<<<dim3(3, rT_N), 256, GSM>>>(th, edgeh, wh_xp2, wh_ep, b_xp2, b_ep,
                                         x, ph, xnh, N, ke);
    // 6: vecnh
    node_elem_k<<<(N * FDIM + 255) / 256, 256>>>(ph, vec, edge_ud, vecnh, N);
    // 7: hx -> out+o0 (xnh residual from smem)
    hgemm2h_k<<<dim3(1, rT_N), 256, GSM3>>>(xnh, wh_sl1, wh_sl2, sB, b_sl2, batch, out + o0, N);
    // 8: hvec -> out+o1 (vecn residual from smem)
    hgemm7_k<<<dim3(1, rT_3N), 256, GSM>>>(vecnh, wh_vl, out + o1, 3 * N, VB, batch);
    // 9: zero sum_x | S | cnt
    {
        int nz = B * 128 + 3 * B * 128 + B;
        zero_k<<<(nz + 255) / 256, 256>>>(sum_x, nz);
    }
    // 10: hx -> sum_x, cnt
    seg_reduce_cnt_k<<<(N + 127) / 128, 128>>>(out + o0, batch, sum_x, cnt, N, 128);
    // 11: vecnh -> S
    seg_reduce_h_k<<<(N + 63) / 64, 384>>>(vecnh, batch, S, N, 64);
    // 12: sum_vec = S@Wvl + S + cnt*VB
    svecfix_k<<<3 * B, 128>>>(S, W_vl, VB, cnt, sum_vec);
    // 13: fused global phase
    global_k<<<B, 128>>>(sum_x, sum_vec, cnt, scalar_l, vector_l,
                         W_sg1, b_sg1, W_sg2, b_sg2, W_vg, W_vp,
                         W_lp1, b_lp1, W_lp2, b_lp2, W_ml,
                         out + o2, out + o3, out + o4);
}

// round 16
// speedup vs baseline: 1.1062x; 1.0597x over previous
#include <cuda_runtime.h>
#include <cuda_fp16.h>
#include <math.h>
#include <stdint.h>

#define FDIM 128
#define SSCALE 1.6666666666666667f   // 1/0.6
#define INV3 0.5773502691896258f     // 1/sqrt(3)
#define INVH 0.08838834764831845f    // 1/sqrt(128)

static __device__ float g_buf[127000000];

__device__ __forceinline__ float ssilu_f(float v) {
    return v * SSCALE / (1.0f + __expf(-v));
}

__device__ __forceinline__ uint32_t pack_h2(float a, float b) {
    __half2 h = __floats2half2_rn(a, b);
    return *reinterpret_cast<uint32_t*>(&h);
}

__device__ __forceinline__ uint32_t smem_to_u32(const void* smem_ptr) {
    uint32_t addr;
    asm("{ .reg .u64 tmp; cvta.to.shared.u64 tmp, %1; cvt.u32.u64 %0, tmp; }"
        : "=r"(addr) : "l"(smem_ptr));
    return addr;
}

__device__ __forceinline__ void ldsm_x4(uint32_t addr, uint32_t* r) {
    asm volatile("ldmatrix.sync.aligned.m8n8.x4.shared.b16 {%0,%1,%2,%3}, [%4];"
        : "=r"(r[0]), "=r"(r[1]), "=r"(r[2]), "=r"(r[3]) : "r"(addr));
}

__device__ __forceinline__ uint32_t lds_u32(uint32_t addr) {
    uint32_t v;
    asm volatile("ld.shared.b32 %0, [%1];" : "=r"(v) : "r"(addr));
    return v;
}

__device__ __forceinline__ void mma_f16(float* d, const uint32_t* a,
                                        const uint32_t* b, const float* c) {
    asm volatile(
        "mma.sync.aligned.m16n8k16.row.col.f32.f16.f16.f32 "
        "{%0,%1,%2,%3},{%4,%5,%6,%7},{%8,%9},{%10,%11,%12,%13};"
        : "=f"(d[0]), "=f"(d[1]), "=f"(d[2]), "=f"(d[3])
        : "r"(a[0]), "r"(a[1]), "r"(a[2]), "r"(a[3]),
          "r"(b[0]), "r"(b[1]),
          "f"(c[0]), "f"(c[1]), "f"(c[2]), "f"(c[3]));
}

__device__ __forceinline__ void cpa16(uint32_t dst, const void* src) {
    asm volatile("cp.async.cg.shared.global [%0], [%1], 16;" :: "r"(dst), "l"(src));
}
#define CP_COMMIT() asm volatile("cp.async.commit_group;" ::: "memory")
#define CP_WAIT0()  asm volatile("cp.async.wait_group 0;" ::: "memory")

__device__ __forceinline__ uint32_t sm_off(int row, int c) {
    uint32_t chunk = (uint32_t)(c & 31) >> 3;
    return (uint32_t)(c >> 5) * 8192 + row * 64
         + ((chunk ^ ((uint32_t)(row >> 1) & 3)) << 4) + ((c & 7) * 2);
}

template <int K>
__device__ __forceinline__ void load_tile(uint32_t sbase, const __half* G,
                                          int grow0, int M, int tid)
{
    constexpr int NCH = K / 8;
    #pragma unroll
    for (int t = 0; t < (128 * NCH) / 256; t++) {
        int id = tid + t * 256;
        int row = id / NCH;
        int ch = id % NCH;
        int ga = grow0 + row;
        if (ga >= M) ga = M - 1;
        uint32_t dst = sbase + (uint32_t)(ch >> 2) * 8192 + row * 64
                     + (((uint32_t)((ch & 3) ^ ((row >> 1) & 3))) << 4);
        cpa16(dst, G + (size_t)ga * K + ch * 8);
    }
}

template <int K>
__device__ __forceinline__ void mma_over_K(
    uint32_t as_b, uint32_t bs_b,
    const uint32_t* a_off, const uint32_t* a_sw,
    const uint32_t* b_off, const uint32_t* b_sw,
    uint32_t a_hi, uint32_t b_hi, float acc[4][4][4])
{
    #pragma unroll
    for (int s4 = 0; s4 < K / 32; s4++) {
        #pragma unroll
        for (int s = 0; s < 2; s++) {
            uint32_t afr[4][4];
            #pragma unroll
            for (int mi = 0; mi < 4; mi++)
                ldsm_x4(as_b + s4 * 8192 + a_off[mi]
                        + (((2 * s + a_hi) ^ a_sw[mi]) << 4), afr[mi]);
            uint32_t bfr[2][4];
            #pragma unroll
            for (int p = 0; p < 2; p++)
                ldsm_x4(bs_b + s4 * 8192 + b_off[p]
                        + (((2 * s + b_hi) ^ b_sw[p]) << 4), bfr[p]);
            #pragma unroll
            for (int mi = 0; mi < 4; mi++)
                #pragma unroll
                for (int nj = 0; nj < 4; nj++)
                    mma_f16(acc[mi][nj], afr[mi],
                            &bfr[nj >> 1][(nj & 1) * 2], acc[mi][nj]);
        }
    }
}

#define ACC_ZERO(A_) \
    _Pragma("unroll") \
    for (int i = 0; i < 4; i++) \
        _Pragma("unroll") \
        for (int j = 0; j < 4; j++) \
            _Pragma("unroll") \
            for (int q = 0; q < 4; q++) (A_)[i][j][q] = 0.0f;

#define FRAG_SETUP() \
    const int tid = threadIdx.x; \
    const int warp = tid >> 5; \
    const int lane = tid & 31; \
    const int wm = warp & 1; \
    const int wn = warp >> 1; \
    const int g = lane >> 2; \
    const int tig = lane & 3; \
    const uint32_t a_hi = lane >> 4; \
    const uint32_t b_hi = (lane >> 3) & 1; \
    uint32_t a_off[4], a_sw[4]; \
    _Pragma("unroll") \
    for (int mi = 0; mi < 4; mi++) { \
        int row = wm * 64 + mi * 16 + (lane & 15); \
        a_off[mi] = row * 64; \
        a_sw[mi] = (row >> 1) & 3; \
    } \
    uint32_t b_off[2], b_sw[2]; \
    _Pragma("unroll") \
    for (int p = 0; p < 2; p++) { \
        int row = wn * 32 + p * 16 + (lane & 7) + ((lane >> 4) ? 8 : 0); \
        b_off[p] = row * 64; \
        b_sw[p] = (row >> 1) & 3; \
    } \
    float acc[4][4][4]; \
    ACC_ZERO(acc)

// ---------------------------------------------------------------------------
__global__ void wtrans_all_k(const float* __restrict__ Wxp1, const float* __restrict__ Wxp2,
                             const float* __restrict__ Wep,  const float* __restrict__ Wsl1,
                             const float* __restrict__ Wsl2, const float* __restrict__ Wvl,
                             __half* __restrict__ dst, int ke)
{
    int id = blockIdx.x * 256 + threadIdx.x;
    int s0 = 16384, s1 = 49152, s2 = 384 * ke, s3 = 16384, s4 = 16384, s5 = 16384;
    const float* W; int K, Cc, off, base;
    if (id < s0) { W = Wxp1; K = 128; Cc = 128; base = 0; off = id; }
    else if (id < s0 + s1) { W = Wxp2; K = 128; Cc = 384; base = s0; off = id - s0; }
    else if (id < s0 + s1 + s2) { W = Wep; K = ke; Cc = 384; base = s0 + s1; off = id - s0 - s1; }
    else if (id < s0 + s1 + s2 + s3) { W = Wsl1; K = 128; Cc = 128; base = s0 + s1 + s2; off = id - s0 - s1 - s2; }
    else if (id < s0 + s1 + s2 + s3 + s4) { W = Wsl2; K = 128; Cc = 128; base = s0 + s1 + s2 + s3; off = id - s0 - s1 - s2 - s3; }
    else if (id < s0 + s1 + s2 + s3 + s4 + s5) { W = Wvl; K = 128; Cc = 128; base = s0 + s1 + s2 + s3 + s4; off = id - s0 - s1 - s2 - s3 - s4; }
    else return;
    int k = off % K, c = off / K;
    dst[base + off] = __float2half(W[(size_t)k * Cc + c]);
}

__global__ void f2h_k(const float* __restrict__ src, __half* __restrict__ dst, int n)
{
    int i = (blockIdx.x * 256 + threadIdx.x) * 8;
    if (i >= n) return;
    float4 a = *reinterpret_cast<const float4*>(src + i);
    float4 b = *reinterpret_cast<const float4*>(src + i + 4);
    uint4 o = make_uint4(pack_h2(a.x, a.y), pack_h2(a.z, a.w),
                         pack_h2(b.x, b.y), pack_h2(b.z, b.w));
    *reinterpret_cast<uint4*>(dst + i) = o;
}

__global__ void __launch_bounds__(128) rowmm_k(
    const float* __restrict__ A, const float* __restrict__ W,
    const float* __restrict__ bias, float* __restrict__ C, int ldw)
{
    int row = blockIdx.x, f = threadIdx.x;
    __shared__ float a_s[128];
    a_s[f] = A[(size_t)row * 128 + f];
    __syncthreads();
    float acc = bias ? bias[f] : 0.0f;
    #pragma unroll 8
    for (int k = 0; k < 128; k++) acc += a_s[k] * W[k * ldw + f];
    C[(size_t)row * 128 + f] = acc;
}

__global__ void __launch_bounds__(128) svecfix_k(
    const float* __restrict__ S, const float* __restrict__ Wvl,
    const float* __restrict__ VB, const float* __restrict__ cnt,
    float* __restrict__ out)
{
    int row = blockIdx.x, f = threadIdx.x;
    int b = row / 3;
    __shared__ float a_s[128];
    a_s[f] = S[(size_t)row * 128 + f];
    __syncthreads();
    float acc = 0.0f;
    #pragma unroll 8
    for (int k = 0; k < 128; k++) acc += a_s[k] * Wvl[k * 128 + f];
    out[(size_t)row * 128 + f] = acc + a_s[f] + cnt[b] * VB[(size_t)row * 128 + f];
}

// ---------------------------------------------------------------------------
// th = ssilu(xh @ Wxp1 + b)  (fp16 out)
// ---------------------------------------------------------------------------
__global__ void __launch_bounds__(256, 2) hgemm_e2_k(
    const __half* __restrict__ A, const __half* __restrict__ WT,
    const float* __restrict__ bias, __half* __restrict__ C, int M)
{
    extern __shared__ char dsm[];
    const uint32_t as_b = smem_to_u32(dsm);
    const uint32_t bs_b = as_b + 32768;
    FRAG_SETUP();
    const int row0 = blockIdx.y * 128;

    load_tile<128>(as_b, A, row0, M, tid);
    load_tile<128>(bs_b, WT, 0, 1 << 30, tid);
    CP_COMMIT(); CP_WAIT0();
    __syncthreads();
    mma_over_K<128>(as_b, bs_b, a_off, a_sw, b_off, b_sw, a_hi, b_hi, acc);

    #pragma unroll
    for (int mi = 0; mi < 4; mi++) {
        int rbase = row0 + wm * 64 + mi * 16 + g;
        #pragma unroll
        for (int half = 0; half < 2; half++) {
            int r = rbase + half * 8;
            if (r >= M) continue;
            #pragma unroll
            for (int nj = 0; nj < 4; nj++) {
                int c = wn * 32 + nj * 8 + tig * 2;
                float v0 = ssilu_f(acc[mi][nj][half * 2 + 0] + bias[c]);
                float v1 = ssilu_f(acc[mi][nj][half * 2 + 1] + bias[c + 1]);
                *reinterpret_cast<uint32_t*>(C + (size_t)r * 128 + c) = pack_h2(v0, v1);
            }
        }
    }
}

// ---------------------------------------------------------------------------
// pgemm: prod = (th@Wxp2+bxp2)*(edgeh@Wep+bep)*INV3
//   cs<2 : ph[N,256] slab ; cs==2: xnh = fp16(prod + x)
// ---------------------------------------------------------------------------
__global__ void __launch_bounds__(256, 2) pgemm_k(
    const __half* __restrict__ Th, const __half* __restrict__ Eh,
    const __half* __restrict__ WTxp2, const __half* __restrict__ WTep,
    const float* __restrict__ bxp2, const float* __restrict__ bep,
    const float* __restrict__ x,
    __half* __restrict__ P, __half* __restrict__ Xnh, int M, int ke)
{
    extern __shared__ char dsm[];
    const uint32_t as_b = smem_to_u32(dsm);
    const uint32_t bs_b = as_b + 32768;
    FRAG_SETUP();
    const int row0 = blockIdx.y * 128;
    const int cs = blockIdx.x;
    const int col0 = cs * 128;

    load_tile<128>(as_b, Th, row0, M, tid);
    load_tile<128>(bs_b, WTxp2, col0, 1 << 30, tid);
    CP_COMMIT(); CP_WAIT0();
    __syncthreads();
    mma_over_K<128>(as_b, bs_b, a_off, a_sw, b_off, b_sw, a_hi, b_hi, acc);

    float acc2[4][4][4];
    ACC_ZERO(acc2);

    __syncthreads();
    load_tile<64>(as_b, Eh, row0, M, tid);
    load_tile<64>(bs_b, WTep, col0, 1 << 30, tid);
    CP_COMMIT(); CP_WAIT0();
    __syncthreads();
    mma_over_K<64>(as_b, bs_b, a_off, a_sw, b_off, b_sw, a_hi, b_hi, acc2);

    #pragma unroll
    for (int mi = 0; mi < 4; mi++) {
        int rbase = row0 + wm * 64 + mi * 16 + g;
        #pragma unroll
        for (int half = 0; half < 2; half++) {
            int r = rbase + half * 8;
            if (r >= M) continue;
            #pragma unroll
            for (int nj = 0; nj < 4; nj++) {
                int lc = wn * 32 + nj * 8 + tig * 2;
                int c = col0 + lc;
                float v0 = (acc[mi][nj][half * 2 + 0] + bxp2[c])
                         * (acc2[mi][nj][half * 2 + 0] + bep[c]) * INV3;
                float v1 = (acc[mi][nj][half * 2 + 1] + bxp2[c + 1])
                         * (acc2[mi][nj][half * 2 + 1] + bep[c + 1]) * INV3;
                if (cs < 2) {
                    *reinterpret_cast<uint32_t*>(P + (size_t)r * 256 + c) = pack_h2(v0, v1);
                } else {
                    v0 += x[(size_t)r * 128 + lc];
                    v1 += x[(size_t)r * 128 + lc + 1];
                    *reinterpret_cast<uint32_t*>(Xnh + (size_t)r * 128 + lc) = pack_h2(v0, v1);
                }
            }
        }
    }
}

// ---------------------------------------------------------------------------
// hvec: vecnh @ Wvl + vecnh(from smem) + VB[gather]  (fp32 out)
// ---------------------------------------------------------------------------
__global__ void __launch_bounds__(256, 2) hgemm7_k(
    const __half* __restrict__ A, const __half* __restrict__ WT,
    float* __restrict__ C, int M,
    const float* __restrict__ extra2, const int* __restrict__ bidx)
{
    extern __shared__ char dsm[];
    const uint32_t as_b = smem_to_u32(dsm);
    const uint32_t bs_b = as_b + 32768;
    FRAG_SETUP();
    const int row0 = blockIdx.y * 128;

    load_tile<128>(as_b, A, row0, M, tid);
    load_tile<128>(bs_b, WT, 0, 1 << 30, tid);
    CP_COMMIT(); CP_WAIT0();
    __syncthreads();
    mma_over_K<128>(as_b, bs_b, a_off, a_sw, b_off, b_sw, a_hi, b_hi, acc);

    #pragma unroll
    for (int mi = 0; mi < 4; mi++) {
        int rloc = wm * 64 + mi * 16 + g;
        #pragma unroll
        for (int half = 0; half < 2; half++) {
            int rl = rloc + half * 8;
            int r = row0 + rl;
            if (r >= M) continue;
            int nnode = r / 3;
            size_t e2off = ((size_t)bidx[nnode] * 3 + (r - nnode * 3)) * 128;
            #pragma unroll
            for (int nj = 0; nj < 4; nj++) {
                int c = wn * 32 + nj * 8 + tig * 2;
                uint32_t eh = lds_u32(as_b + sm_off(rl, c));
                __half2 h2 = *reinterpret_cast<__half2*>(&eh);
                C[(size_t)r * 128 + c]     = acc[mi][nj][half * 2 + 0] + __low2float(h2) + extra2[e2off + c];
                C[(size_t)r * 128 + c + 1] = acc[mi][nj][half * 2 + 1] + __high2float(h2) + extra2[e2off + c + 1];
            }
        }
    }
}

// ---------------------------------------------------------------------------
// hx: u = ssilu(xnh@Wsl1 + sB[bidx]); hx = ssilu(u@Wsl2+b2) + xnh(from smem)
// ---------------------------------------------------------------------------
__global__ void __launch_bounds__(256, 2) hgemm2h_k(
    const __half* __restrict__ A, const __half* __restrict__ WT1,
    const __half* __restrict__ WT2,
    const float* __restrict__ sB, const float* __restrict__ bias2,
    const int* __restrict__ bidx, float* __restrict__ C, int M)
{
    extern __shared__ char dsm[];
    const uint32_t as_b = smem_to_u32(dsm);
    const uint32_t bs_b = as_b + 32768;
    const uint32_t u_b  = as_b + 65536;
    FRAG_SETUP();
    const int row0 = blockIdx.y * 128;

    load_tile<128>(as_b, A, row0, M, tid);
    load_tile<128>(bs_b, WT1, 0, 1 << 30, tid);
    CP_COMMIT(); CP_WAIT0();
    __syncthreads();
    mma_over_K<128>(as_b, bs_b, a_off, a_sw, b_off, b_sw, a_hi, b_hi, acc);

    __syncthreads();
    load_tile<128>(bs_b, WT2, 0, 1 << 30, tid);
    CP_COMMIT();

    #pragma unroll
    for (int mi = 0; mi < 4; mi++) {
        int rloc = wm * 64 + mi * 16 + g;
        #pragma unroll
        for (int half = 0; half < 2; half++) {
            int rl = rloc + half * 8;
            int rg = row0 + rl;
            int rr = rg < M ? rg : M - 1;
            int rb = bidx[rr];
            #pragma unroll
            for (int nj = 0; nj < 4; nj++) {
                int c = wn * 32 + nj * 8 + tig * 2;
                float v0 = ssilu_f(acc[mi][nj][half * 2 + 0] + sB[(size_t)rb * 128 + c]);
                float v1 = ssilu_f(acc[mi][nj][half * 2 + 1] + sB[(size_t)rb * 128 + c + 1]);
                asm volatile("st.shared.b32 [%0], %1;"
                    :: "r"(u_b + sm_off(rl, c)), "r"(pack_h2(v0, v1)));
            }
        }
    }
    CP_WAIT0();
    __syncthreads();

    float acc2[4][4][4];
    ACC_ZERO(acc2);
    mma_over_K<128>(u_b, bs_b, a_off, a_sw, b_off, b_sw, a_hi, b_hi, acc2);

    #pragma unroll
    for (int mi = 0; mi < 4; mi++) {
        int rloc = wm * 64 + mi * 16 + g;
        #pragma unroll
        for (int half = 0; half < 2; half++) {
            int rl = rloc + half * 8;
            int r = row0 + rl;
            if (r >= M) continue;
            #pragma unroll
            for (int nj = 0; nj < 4; nj++) {
                int c = wn * 32 + nj * 8 + tig * 2;
                uint32_t xh2 = lds_u32(as_b + sm_off(rl, c));
                __half2 h2 = *reinterpret_cast<__half2*>(&xh2);
                float v0 = ssilu_f(acc2[mi][nj][half * 2 + 0] + bias2[c]) + __low2float(h2);
                float v1 = ssilu_f(acc2[mi][nj][half * 2 + 1] + bias2[c + 1]) + __high2float(h2);
                C[(size_t)r * 128 + c] = v0;
                C[(size_t)r * 128 + c + 1] = v1;
            }
        }
    }
}

// ---------------------------------------------------------------------------
// node elementwise, half2-vectorized: thread handles 2 columns.
// ---------------------------------------------------------------------------
__global__ void node_elem_k(
    const __half* __restrict__ ph, const float* __restrict__ vec,
    const float* __restrict__ ud, __half* __restrict__ vecnh, int N)
{
    int idx = blockIdx.x * blockDim.x + threadIdx.x;
    if (idx >= N * 64) return;
    int n = idx >> 6;
    int c0 = (idx & 63) * 2;
    size_t b3 = (size_t)n * 384;

    uint32_t p1u = *reinterpret_cast<const uint32_t*>(ph + (size_t)n * 256 + c0);
    uint32_t p2u = *reinterpret_cast<const uint32_t*>(ph + (size_t)n * 256 + 128 + c0);
    __half2 p1h = *reinterpret_cast<__half2*>(&p1u);
    __half2 p2h = *reinterpret_cast<__half2*>(&p2u);
    float p1a = __low2float(p1h), p1b = __high2float(p1h);
    float p2a = __low2float(p2h), p2b = __high2float(p2h);

    float u[3];
    u[0] = ud[n * 3 + 0]; u[1] = ud[n * 3 + 1]; u[2] = ud[n * 3 + 2];

    #pragma unroll
    for (int d = 0; d < 3; d++) {
        float2 v = *reinterpret_cast<const float2*>(vec + b3 + d * 128 + c0);
        float r0 = (p1a * v.x + p2a * u[d]) * INVH;
        float r1 = (p1b * v.y + p2b * u[d]) * INVH;
        *reinterpret_cast<uint32_t*>(vecnh + b3 + d * 128 + c0) = pack_h2(r0, r1);
    }
}

__global__ void zero_k(float* p, int n) {
    int i = blockIdx.x * blockDim.x + threadIdx.x;
    if (i < n) p[i] = 0.0f;
}

__global__ void seg_reduce_cnt_k(const float* src, const int* batch, float* dst,
                                 float* cnt, int N, int rows_per_blk)
{
    int c = threadIdx.x;
    int r0 = blockIdx.x * rows_per_blk;
    if (r0 >= N) return;
    int r1 = min(r0 + rows_per_blk, N);
    int cur = batch[r0];
    float s = 0.0f;
    int runlen = 0;
    for (int r = r0; r < r1; r++) {
        int b = batch[r];
        if (b != cur) {
            atomicAdd(&dst[(size_t)cur * 128 + c], s);
            if (c == 0) atomicAdd(&cnt[cur], (float)runlen);
            s = 0.0f;
            runlen = 0;
            cur = b;
        }
        s += src[(size_t)r * 128 + c];
        runlen++;
    }
    atomicAdd(&dst[(size_t)cur * 128 + c], s);
    if (c == 0) atomicAdd(&cnt[cur], (float)runlen);
}

// fp16-source segment sum, Cc=384, half2-vectorized (192 threads)
__global__ void seg_reduce_h_k(const __half* src, const int* batch, float* dst,
                               int N, int rows_per_blk)
{
    int c = threadIdx.x;          // 0..191 -> columns 2c, 2c+1
    int r0 = blockIdx.x * rows_per_blk;
    if (r0 >= N) return;
    int r1 = min(r0 + rows_per_blk, N);
    int cur = batch[r0];
    float s0 = 0.0f, s1 = 0.0f;
    for (int r = r0; r < r1; r++) {
        int b = batch[r];
        if (b != cur) {
            atomicAdd(&dst[(size_t)cur * 384 + 2 * c], s0);
            atomicAdd(&dst[(size_t)cur * 384 + 2 * c + 1], s1);
            s0 = 0.0f; s1 = 0.0f;
            cur = b;
        }
        uint32_t v = *reinterpret_cast<const uint32_t*>(src + (size_t)r * 384 + 2 * c);
        __half2 h = *reinterpret_cast<__half2*>(&v);
        s0 += __low2float(h);
        s1 += __high2float(h);
    }
    atomicAdd(&dst[(size_t)cur * 384 + 2 * c], s0);
    atomicAdd(&dst[(size_t)cur * 384 + 2 * c + 1], s1);
}

// ---------------------------------------------------------------------------
__global__ void __launch_bounds__(128) global_k(
    const float* __restrict__ sum_x, const float* __restrict__ sum_vec,
    const float* __restrict__ cnt,
    const float* __restrict__ scalar_l, const float* __restrict__ vector_l,
    const float* __restrict__ W_sg1, const float* __restrict__ b_sg1,
    const float* __restrict__ W_sg2, const float* __restrict__ b_sg2,
    const float* __restrict__ W_vg, const float* __restrict__ W_vp,
    const float* __restrict__ W_lp1, const float* __restrict__ b_lp1,
    const float* __restrict__ W_lp2, const float* __restrict__ b_lp2,
    const float* __restrict__ W_ml,
    float* __restrict__ out_sl, float* __restrict__ out_vl,
    float* __restrict__ out_ld)
{
    int b = blockIdx.x;
    int f = threadIdx.x;
    __shared__ float s_g[256];
    __shared__ float s_t[128];
    __shared__ float s_av[3][128];
    __shared__ float s_vl[3][128];
    __shared__ float s_h1[3][128];
    __shared__ float s_red[12];

    float invc = 1.0f / fmaxf(cnt[b], 1.0f);
    size_t bf = (size_t)b * 128 + f;
    float sclf = scalar_l[bf];
    s_g[f] = sum_x[bf] * invc;
    s_g[128 + f] = sclf;
    float vlg[3];
    #pragma unroll
    for (int d = 0; d < 3; d++) {
        size_t o = (size_t)b * 384 + d * 128 + f;
        vlg[d] = vector_l[o];
        s_av[d][f] = sum_vec[o] * invc + vlg[d];
    }
    __syncthreads();

    float acc = b_sg1[f];
    #pragma unroll 8
    for (int k = 0; k < 256; k++) acc += s_g[k] * W_sg1[k * 128 + f];
    s_t[f] = ssilu_f(acc);
    __syncthreads();

    acc = b_sg2[f];
    #pragma unroll 8
    for (int k = 0; k < 128; k++) acc += s_t[k] * W_sg2[k * 128 + f];
    float sl = sclf + ssilu_f(acc);

    float vl[3];
    #pragma unroll
    for (int d = 0; d < 3; d++) {
        float a = 0.0f;
        #pragma unroll 8
        for (int k = 0; k < 128; k++) a += s_av[d][k] * W_vg[k * 128 + f];
        vl[d] = vlg[d] + a;
        s_vl[d][f] = vl[d];
    }
    __syncthreads();

    float vn = 1e-8f;
    #pragma unroll
    for (int d = 0; d < 3; d++) {
        float h1 = 0.0f, h2 = 0.0f;
        #pragma unroll 8
        for (int k = 0; k < 128; k++) {
            float t = s_vl[d][k];
            h1 += t * W_vp[k * 256 + f];
            h2 += t * W_vp[k * 256 + 128 + f];
        }
        s_h1[d][f] = h1;
        vn += h2 * h2;
    }
    s_g[f] = sl;
    s_g[128 + f] = sqrtf(vn);
    __syncthreads();

    acc = b_lp1[f];
    #pragma unroll 8
    for (int k = 0; k < 256; k++) acc += s_g[k] * W_lp1[k * 128 + f];
    s_t[f] = ssilu_f(acc);
    __syncthreads();

    float s1 = b_lp2[f], s2 = b_lp2[128 + f], s3 = b_lp2[256 + f];
    #pragma unroll 4
    for (int k = 0; k < 128; k++) {
        float t = s_t[k];
        s1 += t * W_lp2[k * 384 + f];
        s2 += t * W_lp2[k * 384 + 128 + f];
        s3 += t * W_lp2[k * 384 + 256 + f];
    }
    out_sl[bf] = s2 + sl * tanhf(s3);

    float wml = W_ml[f];
    float part[3];
    #pragma unroll
    for (int d = 0; d < 3; d++) {
        float v = s1 * s_h1[d][f] + vl[d];
        out_vl[(size_t)b * 384 + d * 128 + f] = v;
        part[d] = v * wml;
    }
    #pragma unroll
    for (int d = 0; d < 3; d++)
        #pragma unroll
        for (int o = 16; o; o >>= 1)
            part[d] += __shfl_down_sync(0xffffffff, part[d], o);
    int w = f >> 5, ln = f & 31;
    if (ln == 0) {
        #pragma unroll
        for (int d = 0; d < 3; d++) s_red[d * 4 + w] = part[d];
    }
    __syncthreads();
    if (f < 3)
        out_ld[b * 3 + f] = s_red[f * 4] + s_red[f * 4 + 1]
                          + s_red[f * 4 + 2] + s_red[f * 4 + 3];
}

// ---------------------------------------------------------------------------
extern "C" void kernel_launch(void* const* d_in, const int* in_sizes, int n_in,
                              void* d_out, int out_size)
{
    const float* x        = (const float*)d_in[0];
    const float* scalar_l = (const float*)d_in[1];
    const float* vec      = (const float*)d_in[2];
    const float* vector_l = (const float*)d_in[3];
    const float* edge_f   = (const float*)d_in[4];
    const float* edge_ud  = (const float*)d_in[5];
    const int*   batch    = (const int*)d_in[6];
    const float* W_sg1 = (const float*)d_in[7];  const float* b_sg1 = (const float*)d_in[8];
    const float* W_sg2 = (const float*)d_in[9];  const float* b_sg2 = (const float*)d_in[10];
    const float* W_sl1 = (const float*)d_in[11]; const float* b_sl1 = (const float*)d_in[12];
    const float* W_sl2 = (const float*)d_in[13]; const float* b_sl2 = (const float*)d_in[14];
    const float* W_vg  = (const float*)d_in[15];
    const float* W_vl  = (const float*)d_in[16];
    const float* W_xp1 = (const float*)d_in[17]; const float* b_xp1 = (const float*)d_in[18];
    const float* W_xp2 = (const float*)d_in[19]; const float* b_xp2 = (const float*)d_in[20];
    const float* W_ep  = (const float*)d_in[21]; const float* b_ep  = (const float*)d_in[22];
    const float* W_vp  = (const float*)d_in[23];
    const float* W_lp1 = (const float*)d_in[24]; const float* b_lp1 = (const float*)d_in[25];
    const float* W_lp2 = (const float*)d_in[26]; const float* b_lp2 = (const float*)d_in[27];
    const float* W_ml  = (const float*)d_in[28];

    const int N = in_sizes[0] / FDIM;
    const int B = in_sizes[1] / FDIM;
    const int ke = in_sizes[4] / N;   // 64

    float* base = nullptr;
    cudaGetSymbolAddress((void**)&base, g_buf);

    const size_t NF = (size_t)N * FDIM;
    const size_t NH = (size_t)N * 128;

    __half* hb    = (__half*)base;
    __half* th    = hb;                    // [N,128]
    __half* xnh   = hb + NH;               // [N,128]
    __half* xh    = hb + 2 * NH;           // [N,128]
    __half* vecnh = hb + 3 * NH;           // [3N,128]
    __half* ph    = hb + 6 * NH;           // [N,256]
    __half* edgeh = hb + 8 * NH;           // [N,ke]
    __half* wh    = edgeh + (size_t)N * ke;
    __half* wh_xp1 = wh;
    __half* wh_xp2 = wh + 16384;
    __half* wh_ep  = wh + 65536;
    __half* wh_sl1 = wh + 65536 + 384 * ke;
    __half* wh_sl2 = wh_sl1 + 16384;
    __half* wh_vl  = wh_sl2 + 16384;
    float* smf = (float*)(wh_vl + 16384 + 16);
    float* sum_x   = smf;                        // B*128  (zeroed block start)
    float* S       = sum_x + (size_t)B * 128;    // 3B*128
    float* cnt     = S + (size_t)3 * B * 128;    // B
    float* sB      = cnt + B + 64;               // B*128
    float* VB      = sB + (size_t)B * 128;       // 3B*128
    float* sum_vec = VB + (size_t)3 * B * 128;   // 3B*128

    float* out = (float*)d_out;
    const size_t o0 = 0;
    const size_t o1 = NF;
    const size_t o2 = o1 + 3 * NF;
    const size_t o3 = o2 + (size_t)B * 128;
    const size_t o4 = o3 + (size_t)B * 384;

    const int rT_N  = (N + 127) / 128;
    const int rT_3N = (3 * N + 127) / 128;

    const int GSM = 65536;
    const int GSM3 = 98304;
    cudaFuncSetAttribute(hgemm_e2_k, cudaFuncAttributeMaxDynamicSharedMemorySize, GSM);
    cudaFuncSetAttribute(pgemm_k,    cudaFuncAttributeMaxDynamicSharedMemorySize, GSM);
    cudaFuncSetAttribute(hgemm7_k,   cudaFuncAttributeMaxDynamicSharedMemorySize, GSM);
    cudaFuncSetAttribute(hgemm2h_k,  cudaFuncAttributeMaxDynamicSharedMemorySize, GSM3);

    // 0: all weights -> fp16 transposed
    {
        int tot = 16384 * 4 + 49152 + 384 * ke;
        wtrans_all_k<<<(tot + 255) / 256, 256>>>(W_xp1, W_xp2, W_ep, W_sl1, W_sl2, W_vl, wh, ke);
    }
    // 1-2: input conversions (R13-exact)
    f2h_k<<<((int)(NH / 8) + 255) / 256, 256>>>(x, xh, (int)NH);
    f2h_k<<<((N * ke / 8) + 255) / 256, 256>>>(edge_f, edgeh, N * ke);
    // 3: VB = vector_l @ W_vl (1 row/CTA, R13-exact)
    rowmm_k<<<3 * B, 128>>>(vector_l, W_vl, nullptr, VB, 128);
    // 4: sB = scalar_l @ W_sl1[F:] + b_sl1
    rowmm_k<<<B, 128>>>(scalar_l, W_sl1 + 128 * 128, b_sl1, sB, 128);
    // 5: th = ssilu(xh @ W_xp1 + b_xp1)
    hgemm_e2_k<<<dim3(1, rT_N), 256, GSM>>>(xh, wh_xp1, b_xp1, th, N);
    // 6: ph slabs 0-1, xnh from slab 2
    pgemm_k<<<dim3(3, rT_N), 256, GSM>>>(th, edgeh, wh_xp2, wh_ep, b_xp2, b_ep,
                                         x, ph, xnh, N, ke);
    // 7: vecnh (half2-vectorized)
    node_elem_k<<<(N * 64 + 255) / 256, 256>>>(ph, vec, edge_ud, vecnh, N);
    // 8: hx -> out+o0
    hgemm2h_k<<<dim3(1, rT_N), 256, GSM3>>>(xnh, wh_sl1, wh_sl2, sB, b_sl2, batch, out + o0, N);
    // 9: hvec -> out+o1
    hgemm7_k<<<dim3(1, rT_3N), 256, GSM>>>(vecnh, wh_vl, out + o1, 3 * N, VB, batch);
    // 10: zero sum_x | S | cnt
    {
        int nz = B * 128 + 3 * B * 128 + B;
        zero_k<<<(nz + 255) / 256, 256>>>(sum_x, nz);
    }
    // 11: hx -> sum_x, cnt
    seg_reduce_cnt_k<<<(N + 127) / 128, 128>>>(out + o0, batch, sum_x, cnt, N, 128);
    // 12: vecnh -> S (half2, 192 threads)
    seg_reduce_h_k<<<(N + 63) / 64, 192>>>(vecnh, batch, S, N, 64);
    // 13: sum_vec = S@Wvl + S + cnt*VB
    svecfix_k<<<3 * B, 128>>>(S, W_vl, VB, cnt, sum_vec);
    // 14: fused global phase
    global_k<<<B, 128>>>(sum_x, sum_vec, cnt, scalar_l, vector_l,
                         W_sg1, b_sg1, W_sg2, b_sg2, W_vg, W_vp,
                         W_lp1, b_lp1, W_lp2, b_lp2, W_ml,
                         out + o2, out + o3, out + o4);
}